// round 3
// baseline (speedup 1.0000x reference)
#include <cuda_runtime.h>

#define TT   4
#define NN   20000
#define EE   640000
#define DIN  256
#define DOUT 128
#define SLOPE 0.22916666666666666f

typedef unsigned long long ull;

// ---------------- scratch (__device__ globals; no allocation) ----------------
__device__ float g_scores[TT * NN];
__device__ float g_xt[TT * DIN * DOUT];          // per-t [256][128]
__device__ float g_Wn[(TT + 1) * DIN * DOUT];    // W0 + evolved weights
__device__ float g_WT[6 * DIN * DIN];            // transposed Wz,Uz,Wr,Ur,Wh,Uh
__device__ float g_y[(size_t)TT * NN * DOUT];    // x_t @ Wn_{t+1}  (41 MB)
__device__ int   g_deg[TT * NN];                 // zero-initialized; re-zeroed in scan
__device__ int   g_off[TT * (NN + 1)];
__device__ int   g_cur[TT * NN];
__device__ int2  g_csr[(size_t)TT * EE];         // (src, bits(w)) packed
__device__ int   g_hist[TT * 4096];

// ---------------- helpers ----------------
__device__ __forceinline__ unsigned ord_of(float f) {
    unsigned b = __float_as_uint(f);
    return b ^ ((b & 0x80000000u) ? 0xFFFFFFFFu : 0x80000000u);
}
__device__ __forceinline__ float sigmoidf_(float x) {
    return 1.0f / (1.0f + expf(-x));
}

// ================= L1: front = scores | deg | prep-transpose | hist-zero =====
#define FB_SCORES 10000
#define FB_DEG    10000
#define FB_PREP   1664
#define FB_HZERO  64
#define FB_TOTAL  (FB_SCORES + FB_DEG + FB_PREP + FB_HZERO)

__global__ void front_kernel(const float* __restrict__ embs,
                             const float* __restrict__ p,
                             const float* __restrict__ mask,
                             const int* __restrict__ ei,
                             const float* __restrict__ Wz, const float* __restrict__ Uz,
                             const float* __restrict__ Wr, const float* __restrict__ Ur,
                             const float* __restrict__ Wh, const float* __restrict__ Uh,
                             const float* __restrict__ W0) {
    int b = blockIdx.x;
    int tid = threadIdx.x;
    if (b < FB_SCORES) {
        __shared__ float sp[DIN];
        sp[tid] = p[tid];
        __syncthreads();
        int t = b / 2500;
        int warp = tid >> 5, lane = tid & 31;
        int n = (b % 2500) * 8 + warp;
        const float* xr = embs + ((size_t)t * NN + n) * DIN;
        float4 x0 = *(const float4*)&xr[lane * 4];
        float4 x1 = *(const float4*)&xr[128 + lane * 4];
        float4 p0 = *(const float4*)&sp[lane * 4];
        float4 p1 = *(const float4*)&sp[128 + lane * 4];
        float s = x0.x * p0.x + x0.y * p0.y + x0.z * p0.z + x0.w * p0.w
                + x1.x * p1.x + x1.y * p1.y + x1.z * p1.z + x1.w * p1.w;
        float q = p0.x * p0.x + p0.y * p0.y + p0.z * p0.z + p0.w * p0.w
                + p1.x * p1.x + p1.y * p1.y + p1.z * p1.z + p1.w * p1.w;
#pragma unroll
        for (int o = 16; o > 0; o >>= 1) {
            s += __shfl_down_sync(0xFFFFFFFFu, s, o);
            q += __shfl_down_sync(0xFFFFFFFFu, q, o);
        }
        if (lane == 0) g_scores[t * NN + n] = s * rsqrtf(q) + mask[t * NN + n];
    } else if (b < FB_SCORES + FB_DEG) {
        int idx = b - FB_SCORES;
        int t = idx / 2500;
        int e = (idx % 2500) * 256 + tid;
        const int* dst = ei + (size_t)t * 2 * EE;
        atomicAdd(&g_deg[t * NN + dst[e]], 1);
    } else if (b < FB_SCORES + FB_DEG + FB_PREP) {
        int idx = (b - FB_SCORES - FB_DEG) * 256 + tid;
        const float* srcs[6] = {Wz, Uz, Wr, Ur, Wh, Uh};
        if (idx < 6 * DIN * DIN) {
            int m = idx >> 16;
            int e = idx & 0xFFFF;
            int k = e >> 8, i = e & 255;
            g_WT[idx] = srcs[m][i * DIN + k];
        } else {
            int e = idx - 6 * DIN * DIN;
            g_Wn[e] = W0[e];
        }
    } else {
        int i = (b - FB_SCORES - FB_DEG - FB_PREP) * 256 + tid;
        if (i < TT * 4096) g_hist[i] = 0;
    }
}

// ================= L2: mid1 = hist(32 blocks) | scan(4 blocks) ================
__device__ void do_scan(int t) {
    __shared__ int part[1024];
    int tid = threadIdx.x;
    int* deg = g_deg + t * NN;
    int* off = g_off + t * (NN + 1);
    int* cur = g_cur + t * NN;
    int base = tid * 20;
    int loc[20];
    int sum = 0;
#pragma unroll
    for (int i = 0; i < 20; i++) {
        int n = base + i;
        int d = (n < NN) ? deg[n] : 0;
        if (n < NN) deg[n] = 0;     // re-zero for next graph replay
        loc[i] = sum;
        sum += d;
    }
    part[tid] = sum;
    __syncthreads();
    for (int o = 1; o < 1024; o <<= 1) {
        int v = (tid >= o) ? part[tid - o] : 0;
        __syncthreads();
        part[tid] += v;
        __syncthreads();
    }
    int myoff = tid ? part[tid - 1] : 0;
#pragma unroll
    for (int i = 0; i < 20; i++) {
        int n = base + i;
        if (n <= NN) {
            int o = myoff + loc[i];
            off[n] = o;
            if (n < NN) cur[n] = o;
        }
    }
}

__global__ void mid1_kernel() {
    int b = blockIdx.x;
    int tid = threadIdx.x;   // 1024
    if (b < 32) {
        __shared__ int h[4096];
        int t = b >> 3, chunk = b & 7;
#pragma unroll
        for (int j = 0; j < 4; j++) h[tid + j * 1024] = 0;
        __syncthreads();
        const float* scores = g_scores + t * NN;
        int base = chunk * 2500;
        for (int n = base + tid; n < base + 2500; n += 1024)
            atomicAdd(&h[ord_of(scores[n]) >> 20], 1);
        __syncthreads();
#pragma unroll
        for (int j = 0; j < 4; j++) {
            int bin = tid + j * 1024;
            int v = h[bin];
            if (v) atomicAdd(&g_hist[t * 4096 + bin], v);
        }
    } else {
        do_scan(b - 32);
    }
}

// ================= L3: mid2 = per-t select + xt build ========================
__global__ void mid2_kernel(const float* __restrict__ embs) {
    int t = blockIdx.x;
    int tid = threadIdx.x;   // 1024
    __shared__ int part[1024];
    __shared__ int sB, sAbove;
    __shared__ unsigned cnt_gt, cnt_cand;
    __shared__ unsigned sel_ord[DOUT];
    __shared__ int sel_idx[DOUT];
    __shared__ unsigned cand_ord[512];
    __shared__ int cand_idx[512];
    __shared__ int sh_idx[DOUT];
    __shared__ float sh_tanh[DOUT];

    const float* scores = g_scores + t * NN;
    const int* hist = g_hist + t * 4096;

    int cnt[4];
    int s = 0;
#pragma unroll
    for (int j = 0; j < 4; j++) {
        int bin = 4095 - (tid * 4 + j);   // descending order
        cnt[j] = hist[bin];
        s += cnt[j];
    }
    part[tid] = s;
    if (tid == 0) { cnt_gt = 0; cnt_cand = 0; }
    __syncthreads();
    for (int o = 1; o < 1024; o <<= 1) {
        int v = (tid >= o) ? part[tid - o] : 0;
        __syncthreads();
        part[tid] += v;
        __syncthreads();
    }
    int c = tid ? part[tid - 1] : 0;
#pragma unroll
    for (int j = 0; j < 4; j++) {
        int bin = 4095 - (tid * 4 + j);
        if (c < DOUT && c + cnt[j] >= DOUT) { sB = bin; sAbove = c; }
        c += cnt[j];
    }
    __syncthreads();
    int B = sB, above = sAbove, kneed = DOUT - above;

    for (int n = tid; n < NN; n += 1024) {
        unsigned ord = ord_of(scores[n]);
        int bucket = ord >> 20;
        if (bucket > B) {
            unsigned pos = atomicAdd(&cnt_gt, 1u);
            sel_ord[pos] = ord; sel_idx[pos] = n;
        } else if (bucket == B) {
            unsigned pos = atomicAdd(&cnt_cand, 1u);
            if (pos < 512) { cand_ord[pos] = ord; cand_idx[pos] = n; }
        }
    }
    __syncthreads();
    int nc = (int)cnt_cand; if (nc > 512) nc = 512;
    for (int ci = tid; ci < nc; ci += 1024) {
        unsigned mo = cand_ord[ci];
        int mi = cand_idx[ci];
        int r = 0;
        for (int j = 0; j < nc; j++) {
            unsigned o = cand_ord[j];
            r += (o > mo) || (o == mo && cand_idx[j] < mi);
        }
        if (r < kneed) { sel_ord[above + r] = mo; sel_idx[above + r] = mi; }
    }
    __syncthreads();
    if (tid < DOUT) {
        unsigned mo = sel_ord[tid];
        int mi = sel_idx[tid];
        int r = 0;
#pragma unroll 4
        for (int i = 0; i < DOUT; i++) {
            unsigned o = sel_ord[i];
            r += (o > mo) || (o == mo && sel_idx[i] < mi);
        }
        sh_idx[r] = mi;
        sh_tanh[r] = tanhf(scores[mi]);
    }
    __syncthreads();
    float* xt = g_xt + t * DIN * DOUT;
    for (int e = tid; e < DIN * DOUT; e += 1024) {
        int j = e >> 8;
        int d = e & 255;
        xt[d * DOUT + j] = embs[((size_t)t * NN + sh_idx[j]) * DIN + d] * sh_tanh[j];
    }
}

// ================= L4: grufill = gru(32 blocks, all 4 t) | fill(10000) ========
#define GCOLS 4
__device__ __forceinline__ void dev_gru(int bx,
                                        const float* __restrict__ bz,
                                        const float* __restrict__ br,
                                        const float* __restrict__ bh) {
    __shared__ __align__(16) float xts[DIN * GCOLS];
    __shared__ __align__(16) float Ws[DIN * GCOLS];
    __shared__ __align__(16) float rws[DIN * GCOLS];
    int i = threadIdx.x;         // 0..255
    int j0 = bx * GCOLS;         // 32 blocks
    const float* WzT = g_WT + 0 * DIN * DIN;
    const float* UzT = g_WT + 1 * DIN * DIN;
    const float* WrT = g_WT + 2 * DIN * DIN;
    const float* UrT = g_WT + 3 * DIN * DIN;
    const float* WhT = g_WT + 4 * DIN * DIN;
    const float* UhT = g_WT + 5 * DIN * DIN;
    float bzv[GCOLS], brv[GCOLS], bhv[GCOLS];
#pragma unroll
    for (int cc = 0; cc < GCOLS; cc++) {
        Ws[i * GCOLS + cc] = g_Wn[i * DOUT + j0 + cc];
        bzv[cc] = bz[i * DOUT + j0 + cc];
        brv[cc] = br[i * DOUT + j0 + cc];
        bhv[cc] = bh[i * DOUT + j0 + cc];
    }
    for (int t = 0; t < TT; t++) {
        const float* xt = g_xt + t * DIN * DOUT;
#pragma unroll
        for (int cc = 0; cc < GCOLS; cc++)
            xts[i * GCOLS + cc] = xt[i * DOUT + j0 + cc];
        __syncthreads();

        float az[GCOLS] = {0, 0, 0, 0}, ar[GCOLS] = {0, 0, 0, 0};
#pragma unroll 4
        for (int k = 0; k < DIN; k++) {
            float wz = WzT[k * DIN + i], uz = UzT[k * DIN + i];
            float wr = WrT[k * DIN + i], ur = UrT[k * DIN + i];
            float4 xv = *(const float4*)&xts[k * GCOLS];
            float4 wv = *(const float4*)&Ws[k * GCOLS];
            az[0] += wz * xv.x + uz * wv.x;  ar[0] += wr * xv.x + ur * wv.x;
            az[1] += wz * xv.y + uz * wv.y;  ar[1] += wr * xv.y + ur * wv.y;
            az[2] += wz * xv.z + uz * wv.z;  ar[2] += wr * xv.z + ur * wv.z;
            az[3] += wz * xv.w + uz * wv.w;  ar[3] += wr * xv.w + ur * wv.w;
        }
        float z[GCOLS], r[GCOLS];
#pragma unroll
        for (int cc = 0; cc < GCOLS; cc++) {
            z[cc] = sigmoidf_(az[cc] + bzv[cc]);
            r[cc] = sigmoidf_(ar[cc] + brv[cc]);
            rws[i * GCOLS + cc] = r[cc] * Ws[i * GCOLS + cc];
        }
        __syncthreads();

        float ah[GCOLS] = {0, 0, 0, 0};
#pragma unroll 4
        for (int k = 0; k < DIN; k++) {
            float wh = WhT[k * DIN + i], uh = UhT[k * DIN + i];
            float4 xv = *(const float4*)&xts[k * GCOLS];
            float4 rv = *(const float4*)&rws[k * GCOLS];
            ah[0] += wh * xv.x + uh * rv.x;
            ah[1] += wh * xv.y + uh * rv.y;
            ah[2] += wh * xv.z + uh * rv.z;
            ah[3] += wh * xv.w + uh * rv.w;
        }
        float* Wnext = g_Wn + (t + 1) * DIN * DOUT;
#pragma unroll
        for (int cc = 0; cc < GCOLS; cc++) {
            float h = tanhf(ah[cc] + bhv[cc]);
            float Wv = Ws[i * GCOLS + cc];
            float wn = (1.0f - z[cc]) * Wv + z[cc] * h;
            Wnext[i * DOUT + j0 + cc] = wn;
            Ws[i * GCOLS + cc] = wn;
        }
        __syncthreads();
    }
}

__global__ void grufill_kernel(const int* __restrict__ ei, const float* __restrict__ w,
                               const float* __restrict__ bz, const float* __restrict__ br,
                               const float* __restrict__ bh) {
    int b = blockIdx.x;
    if (b < 32) {
        dev_gru(b, bz, br, bh);
    } else {
        int idx = b - 32;
        int t = idx / 2500;
        int e = (idx % 2500) * 256 + threadIdx.x;
        const int* dst = ei + (size_t)t * 2 * EE;
        const int* src = dst + EE;
        int d = dst[e];
        int pos = atomicAdd(&g_cur[t * NN + d], 1);
        g_csr[(size_t)t * EE + pos] = make_int2(src[e], __float_as_int(w[(size_t)t * EE + e]));
    }
}

// ================= sgemm / gather block bodies ================================
#define BM 128
#define BN 128
#define BK 32
#define SGB 157   // sgemm blocks per t

__device__ __forceinline__ void dev_sgemm(int t, int bx, const float* __restrict__ embs,
                                          float As[BK][BM + 1], float Bs[BK][BN]) {
    const float* A = embs + (size_t)t * NN * DIN;
    const float* B = g_Wn + (t + 1) * DIN * DOUT;
    float* C = g_y + (size_t)t * NN * DOUT;

    int tid = threadIdx.x;           // 256
    int bm = bx * BM;
    int tx = tid & 15;               // cols tx*2 + 32*j
    int ty = tid >> 4;               // rows ty*8..+7
    int ar = tid >> 3;               // A-load row
    int ac = (tid & 7) * 4;          // A-load k quad

    ull acc[8][4];
#pragma unroll
    for (int m = 0; m < 8; m++)
#pragma unroll
        for (int j = 0; j < 4; j++) acc[m][j] = 0ull;

    float4 pa[4], pb[4];
#pragma unroll
    for (int pass = 0; pass < 4; pass++) {
        int gr = bm + pass * 32 + ar;
        pa[pass] = (gr < NN) ? *(const float4*)&A[(size_t)gr * DIN + ac]
                             : make_float4(0.f, 0.f, 0.f, 0.f);
        int q = pass * 256 + tid;
        pb[pass] = *(const float4*)&B[(q >> 5) * BN + (q & 31) * 4];
    }

    for (int k0 = 0; k0 < DIN; k0 += BK) {
#pragma unroll
        for (int pass = 0; pass < 4; pass++) {
            int r = pass * 32 + ar;
            As[ac + 0][r] = pa[pass].x;
            As[ac + 1][r] = pa[pass].y;
            As[ac + 2][r] = pa[pass].z;
            As[ac + 3][r] = pa[pass].w;
            int q = pass * 256 + tid;
            *(float4*)&Bs[q >> 5][(q & 31) * 4] = pb[pass];
        }
        __syncthreads();
        int kn = k0 + BK;
        if (kn < DIN) {
#pragma unroll
            for (int pass = 0; pass < 4; pass++) {
                int gr = bm + pass * 32 + ar;
                pa[pass] = (gr < NN) ? *(const float4*)&A[(size_t)gr * DIN + kn + ac]
                                     : make_float4(0.f, 0.f, 0.f, 0.f);
                int q = pass * 256 + tid;
                pb[pass] = *(const float4*)&B[(kn + (q >> 5)) * BN + (q & 31) * 4];
            }
        }
#pragma unroll
        for (int kk = 0; kk < BK; kk++) {
            ull b2[4];
#pragma unroll
            for (int j = 0; j < 4; j++)
                b2[j] = *(const ull*)&Bs[kk][tx * 2 + 32 * j];
#pragma unroll
            for (int m = 0; m < 8; m++) {
                float a = As[kk][ty * 8 + m];
                ull a2;
                asm("mov.b64 %0, {%1, %1};" : "=l"(a2) : "f"(a));
#pragma unroll
                for (int j = 0; j < 4; j++)
                    asm("fma.rn.f32x2 %0, %1, %2, %0;"
                        : "+l"(acc[m][j]) : "l"(a2), "l"(b2[j]));
            }
        }
        __syncthreads();
    }
#pragma unroll
    for (int m = 0; m < 8; m++) {
        int gr = bm + ty * 8 + m;
        if (gr < NN) {
#pragma unroll
            for (int j = 0; j < 4; j++)
                *(ull*)&C[(size_t)gr * DOUT + tx * 2 + 32 * j] = acc[m][j];
        }
    }
}

__device__ __forceinline__ void dev_gather(int t, int bx, float* __restrict__ out) {
    int node = bx * 8 + (threadIdx.x >> 5);
    int lane = threadIdx.x & 31;
    const int* off = g_off + t * (NN + 1);
    const int2* csr = g_csr + (size_t)t * EE;
    const float* y = g_y + (size_t)t * NN * DOUT;
    int beg = off[node], end = off[node + 1];
    float4 acc = make_float4(0.f, 0.f, 0.f, 0.f);
    int e = beg;
    for (; e + 4 <= end; e += 4) {
        int2 c0 = csr[e + 0], c1 = csr[e + 1], c2 = csr[e + 2], c3 = csr[e + 3];
        float4 v0 = *(const float4*)&y[(size_t)c0.x * DOUT + lane * 4];
        float4 v1 = *(const float4*)&y[(size_t)c1.x * DOUT + lane * 4];
        float4 v2 = *(const float4*)&y[(size_t)c2.x * DOUT + lane * 4];
        float4 v3 = *(const float4*)&y[(size_t)c3.x * DOUT + lane * 4];
        float w0 = __int_as_float(c0.y), w1 = __int_as_float(c1.y);
        float w2 = __int_as_float(c2.y), w3 = __int_as_float(c3.y);
        acc.x += w0 * v0.x + w1 * v1.x + w2 * v2.x + w3 * v3.x;
        acc.y += w0 * v0.y + w1 * v1.y + w2 * v2.y + w3 * v3.y;
        acc.z += w0 * v0.z + w1 * v1.z + w2 * v2.z + w3 * v3.z;
        acc.w += w0 * v0.w + w1 * v1.w + w2 * v2.w + w3 * v3.w;
    }
    for (; e < end; e++) {
        int2 c0 = csr[e];
        float w0 = __int_as_float(c0.y);
        float4 v0 = *(const float4*)&y[(size_t)c0.x * DOUT + lane * 4];
        acc.x += w0 * v0.x; acc.y += w0 * v0.y; acc.z += w0 * v0.z; acc.w += w0 * v0.w;
    }
    acc.x = (acc.x >= 0.f) ? acc.x : SLOPE * acc.x;
    acc.y = (acc.y >= 0.f) ? acc.y : SLOPE * acc.y;
    acc.z = (acc.z >= 0.f) ? acc.z : SLOPE * acc.z;
    acc.w = (acc.w >= 0.f) ? acc.w : SLOPE * acc.w;
    *(float4*)&out[((size_t)t * NN + node) * DOUT + lane * 4] = acc;
}

// ================= pipelined launches =========================================
__global__ __launch_bounds__(256, 2) void sgemm_only_kernel(int t, const float* __restrict__ embs) {
    __shared__ __align__(16) float As[BK][BM + 1];
    __shared__ __align__(16) float Bs[BK][BN];
    dev_sgemm(t, blockIdx.x, embs, As, Bs);
}

__global__ __launch_bounds__(256, 2) void sg_both_kernel(int t_sg, int t_ga,
                                                         const float* __restrict__ embs,
                                                         float* __restrict__ out) {
    __shared__ __align__(16) float As[BK][BM + 1];
    __shared__ __align__(16) float Bs[BK][BN];
    if (blockIdx.x < 2500) dev_gather(t_ga, blockIdx.x, out);
    else                   dev_sgemm(t_sg, blockIdx.x - 2500, embs, As, Bs);
}

__global__ void gather_only_kernel(int t, float* __restrict__ out) {
    dev_gather(t, blockIdx.x, out);
}

// ---------------- launcher ----------------
extern "C" void kernel_launch(void* const* d_in, const int* in_sizes, int n_in,
                              void* d_out, int out_size) {
    const float* node_embs  = (const float*)d_in[0];   // [T,N,256]
    const int*   edge_index = (const int*)d_in[1];     // [T,2,E]
    const float* edge_w     = (const float*)d_in[2];   // [T,E]
    const float* mask       = (const float*)d_in[3];   // [T,N]
    const float* p          = (const float*)d_in[4];   // [256,1]
    const float* Wz         = (const float*)d_in[5];
    const float* Uz         = (const float*)d_in[6];
    const float* bz         = (const float*)d_in[7];
    const float* Wr         = (const float*)d_in[8];
    const float* Ur         = (const float*)d_in[9];
    const float* br         = (const float*)d_in[10];
    const float* Wh         = (const float*)d_in[11];
    const float* Uh         = (const float*)d_in[12];
    const float* bh         = (const float*)d_in[13];
    const float* W0         = (const float*)d_in[14];
    float* out = (float*)d_out;                        // [T,N,128]

    front_kernel<<<FB_TOTAL, 256>>>(node_embs, p, mask, edge_index,
                                    Wz, Uz, Wr, Ur, Wh, Uh, W0);
    mid1_kernel<<<36, 1024>>>();
    mid2_kernel<<<4, 1024>>>(node_embs);
    grufill_kernel<<<32 + 10000, 256>>>(edge_index, edge_w, bz, br, bh);

    sgemm_only_kernel<<<SGB, 256>>>(0, node_embs);
    sg_both_kernel<<<2500 + SGB, 256>>>(1, 0, node_embs, out);
    sg_both_kernel<<<2500 + SGB, 256>>>(2, 1, node_embs, out);
    sg_both_kernel<<<2500 + SGB, 256>>>(3, 2, node_embs, out);
    gather_only_kernel<<<2500, 256>>>(3, out);
}

// round 4
// speedup vs baseline: 1.2133x; 1.2133x over previous
#include <cuda_runtime.h>

#define TT   4
#define NN   20000
#define EE   640000
#define DIN  256
#define DOUT 128
#define MAT  (DIN * DOUT)      // 32768
#define MSQ  (DIN * DIN)       // 65536
#define SLOPE 0.22916666666666666f

typedef unsigned long long ull;

// ---------------- scratch (__device__ globals; no allocation) ----------------
__device__ float g_scores[TT * NN];
__device__ float g_xt[TT * MAT];             // per-t [256][128]
__device__ float g_Wn[(TT + 1) * MAT];       // W0 + evolved weights
__device__ float g_WT[6 * MSQ];              // transposed Wz,Uz,Wr,Ur,Wh,Uh
__device__ float g_WX[3 * TT * MAT];         // Wz@xt, Wr@xt, Wh@xt per t
__device__ float g_z[MAT];
__device__ float g_rW[MAT];
__device__ float g_y[(size_t)TT * NN * DOUT];
__device__ int   g_deg[TT * NN];
__device__ int   g_off[TT * (NN + 1)];
__device__ int   g_cur[TT * NN];
__device__ int2  g_csr[(size_t)TT * EE];
__device__ int   g_hist[TT * 4096];

// ---------------- helpers ----------------
__device__ __forceinline__ unsigned ord_of(float f) {
    unsigned b = __float_as_uint(f);
    return b ^ ((b & 0x80000000u) ? 0xFFFFFFFFu : 0x80000000u);
}
__device__ __forceinline__ float sigmoidf_(float x) {
    return 1.0f / (1.0f + expf(-x));
}
__device__ __forceinline__ float2 upk(ull v) {
    float2 r;
    asm("mov.b64 {%0, %1}, %2;" : "=f"(r.x), "=f"(r.y) : "l"(v));
    return r;
}
__device__ __forceinline__ ull dup2(float a) {
    ull r;
    asm("mov.b64 %0, {%1, %1};" : "=l"(r) : "f"(a));
    return r;
}

// ================= L1: front = scores | deg | prep-transpose | hist-zero =====
#define FB_SCORES 10000
#define FB_DEG    10000
#define FB_PREP   1664
#define FB_HZERO  64
#define FB_TOTAL  (FB_SCORES + FB_DEG + FB_PREP + FB_HZERO)

__global__ void front_kernel(const float* __restrict__ embs,
                             const float* __restrict__ p,
                             const float* __restrict__ mask,
                             const int* __restrict__ ei,
                             const float* __restrict__ Wz, const float* __restrict__ Uz,
                             const float* __restrict__ Wr, const float* __restrict__ Ur,
                             const float* __restrict__ Wh, const float* __restrict__ Uh,
                             const float* __restrict__ W0) {
    int b = blockIdx.x;
    int tid = threadIdx.x;
    if (b < FB_SCORES) {
        __shared__ float sp[DIN];
        sp[tid] = p[tid];
        __syncthreads();
        int t = b / 2500;
        int warp = tid >> 5, lane = tid & 31;
        int n = (b % 2500) * 8 + warp;
        const float* xr = embs + ((size_t)t * NN + n) * DIN;
        float4 x0 = *(const float4*)&xr[lane * 4];
        float4 x1 = *(const float4*)&xr[128 + lane * 4];
        float4 p0 = *(const float4*)&sp[lane * 4];
        float4 p1 = *(const float4*)&sp[128 + lane * 4];
        float s = x0.x * p0.x + x0.y * p0.y + x0.z * p0.z + x0.w * p0.w
                + x1.x * p1.x + x1.y * p1.y + x1.z * p1.z + x1.w * p1.w;
        float q = p0.x * p0.x + p0.y * p0.y + p0.z * p0.z + p0.w * p0.w
                + p1.x * p1.x + p1.y * p1.y + p1.z * p1.z + p1.w * p1.w;
#pragma unroll
        for (int o = 16; o > 0; o >>= 1) {
            s += __shfl_down_sync(0xFFFFFFFFu, s, o);
            q += __shfl_down_sync(0xFFFFFFFFu, q, o);
        }
        if (lane == 0) g_scores[t * NN + n] = s * rsqrtf(q) + mask[t * NN + n];
    } else if (b < FB_SCORES + FB_DEG) {
        int idx = b - FB_SCORES;
        int t = idx / 2500;
        int e = (idx % 2500) * 256 + tid;
        const int* dst = ei + (size_t)t * 2 * EE;
        atomicAdd(&g_deg[t * NN + dst[e]], 1);
    } else if (b < FB_SCORES + FB_DEG + FB_PREP) {
        int idx = (b - FB_SCORES - FB_DEG) * 256 + tid;
        const float* srcs[6] = {Wz, Uz, Wr, Ur, Wh, Uh};
        if (idx < 6 * MSQ) {
            int m = idx >> 16;
            int e = idx & 0xFFFF;
            int k = e >> 8, i = e & 255;
            g_WT[idx] = srcs[m][i * DIN + k];
        } else {
            int e = idx - 6 * MSQ;
            g_Wn[e] = W0[e];
        }
    } else {
        int i = (b - FB_SCORES - FB_DEG - FB_PREP) * 256 + tid;
        if (i < TT * 4096) g_hist[i] = 0;
    }
}

// ================= L2: mid1 = hist(32 blocks) | scan(4 blocks) ================
__device__ void do_scan(int t) {
    __shared__ int part[1024];
    int tid = threadIdx.x;
    int* deg = g_deg + t * NN;
    int* off = g_off + t * (NN + 1);
    int* cur = g_cur + t * NN;
    int base = tid * 20;
    int loc[20];
    int sum = 0;
#pragma unroll
    for (int i = 0; i < 20; i++) {
        int n = base + i;
        int d = (n < NN) ? deg[n] : 0;
        if (n < NN) deg[n] = 0;     // re-zero for graph replay
        loc[i] = sum;
        sum += d;
    }
    part[tid] = sum;
    __syncthreads();
    for (int o = 1; o < 1024; o <<= 1) {
        int v = (tid >= o) ? part[tid - o] : 0;
        __syncthreads();
        part[tid] += v;
        __syncthreads();
    }
    int myoff = tid ? part[tid - 1] : 0;
#pragma unroll
    for (int i = 0; i < 20; i++) {
        int n = base + i;
        if (n <= NN) {
            int o = myoff + loc[i];
            off[n] = o;
            if (n < NN) cur[n] = o;
        }
    }
}

__global__ void mid1_kernel() {
    int b = blockIdx.x;
    int tid = threadIdx.x;   // 1024
    if (b < 32) {
        __shared__ int h[4096];
        int t = b >> 3, chunk = b & 7;
#pragma unroll
        for (int j = 0; j < 4; j++) h[tid + j * 1024] = 0;
        __syncthreads();
        const float* scores = g_scores + t * NN;
        int base = chunk * 2500;
        for (int n = base + tid; n < base + 2500; n += 1024)
            atomicAdd(&h[ord_of(scores[n]) >> 20], 1);
        __syncthreads();
#pragma unroll
        for (int j = 0; j < 4; j++) {
            int bin = tid + j * 1024;
            int v = h[bin];
            if (v) atomicAdd(&g_hist[t * 4096 + bin], v);
        }
    } else {
        do_scan(b - 32);
    }
}

// ================= L3: mid2 = per-t select + xt build ========================
__global__ void mid2_kernel(const float* __restrict__ embs) {
    int t = blockIdx.x;
    int tid = threadIdx.x;   // 1024
    __shared__ int part[1024];
    __shared__ int sB, sAbove;
    __shared__ unsigned cnt_gt, cnt_cand;
    __shared__ unsigned sel_ord[DOUT];
    __shared__ int sel_idx[DOUT];
    __shared__ unsigned cand_ord[512];
    __shared__ int cand_idx[512];
    __shared__ int sh_idx[DOUT];
    __shared__ float sh_tanh[DOUT];

    const float* scores = g_scores + t * NN;
    const int* hist = g_hist + t * 4096;

    int cnt[4];
    int s = 0;
#pragma unroll
    for (int j = 0; j < 4; j++) {
        int bin = 4095 - (tid * 4 + j);
        cnt[j] = hist[bin];
        s += cnt[j];
    }
    part[tid] = s;
    if (tid == 0) { cnt_gt = 0; cnt_cand = 0; }
    __syncthreads();
    for (int o = 1; o < 1024; o <<= 1) {
        int v = (tid >= o) ? part[tid - o] : 0;
        __syncthreads();
        part[tid] += v;
        __syncthreads();
    }
    int c = tid ? part[tid - 1] : 0;
#pragma unroll
    for (int j = 0; j < 4; j++) {
        int bin = 4095 - (tid * 4 + j);
        if (c < DOUT && c + cnt[j] >= DOUT) { sB = bin; sAbove = c; }
        c += cnt[j];
    }
    __syncthreads();
    int B = sB, above = sAbove, kneed = DOUT - above;

    for (int n = tid; n < NN; n += 1024) {
        unsigned ord = ord_of(scores[n]);
        int bucket = ord >> 20;
        if (bucket > B) {
            unsigned pos = atomicAdd(&cnt_gt, 1u);
            sel_ord[pos] = ord; sel_idx[pos] = n;
        } else if (bucket == B) {
            unsigned pos = atomicAdd(&cnt_cand, 1u);
            if (pos < 512) { cand_ord[pos] = ord; cand_idx[pos] = n; }
        }
    }
    __syncthreads();
    int nc = (int)cnt_cand; if (nc > 512) nc = 512;
    for (int ci = tid; ci < nc; ci += 1024) {
        unsigned mo = cand_ord[ci];
        int mi = cand_idx[ci];
        int r = 0;
        for (int j = 0; j < nc; j++) {
            unsigned o = cand_ord[j];
            r += (o > mo) || (o == mo && cand_idx[j] < mi);
        }
        if (r < kneed) { sel_ord[above + r] = mo; sel_idx[above + r] = mi; }
    }
    __syncthreads();
    if (tid < DOUT) {
        unsigned mo = sel_ord[tid];
        int mi = sel_idx[tid];
        int r = 0;
#pragma unroll 4
        for (int i = 0; i < DOUT; i++) {
            unsigned o = sel_ord[i];
            r += (o > mo) || (o == mo && sel_idx[i] < mi);
        }
        sh_idx[r] = mi;
        sh_tanh[r] = tanhf(scores[mi]);
    }
    __syncthreads();
    float* xt = g_xt + t * MAT;
    for (int e = tid; e < MAT; e += 1024) {
        int j = e >> 8;
        int d = e & 255;
        xt[d * DOUT + j] = embs[((size_t)t * NN + sh_idx[j]) * DIN + d] * sh_tanh[j];
    }
}

// ================= small GEMM: 16x128 tile, K=256, up to 3 A-mats sharing B ===
#define KT 32
// smem layout: Bs[32][128] (16KB) then As[NMAT*32][16]
template <int NMAT>
__device__ __forceinline__ void gemm16(const float* __restrict__ AT0,
                                       const float* __restrict__ AT1,
                                       const float* __restrict__ AT2,
                                       const float* __restrict__ Bmat,
                                       int i0, ull a0[4], ull a1[4], ull a2[4],
                                       char* sm) {
    float (*Bs)[128] = (float(*)[128])sm;
    float (*As)[16]  = (float(*)[16])(sm + KT * 128 * 4);
    int tid = threadIdx.x;           // 256
    int ti = tid & 15, tj = tid >> 4;
    int brow = tid >> 5, bcol = (tid & 31) * 4;
    int akk = tid >> 4, aii = tid & 15;

    float4 pb[4];
    float pa0[2], pa1[2], pa2[2];
#pragma unroll
    for (int l = 0; l < 4; l++)
        pb[l] = *(const float4*)&Bmat[(brow + 8 * l) * 128 + bcol];
#pragma unroll
    for (int l = 0; l < 2; l++) {
        int kk = akk + 16 * l;
        pa0[l] = AT0[kk * DIN + i0 + aii];
        if (NMAT > 1) pa1[l] = AT1[kk * DIN + i0 + aii];
        if (NMAT > 2) pa2[l] = AT2[kk * DIN + i0 + aii];
    }
    for (int k0 = 0; k0 < DIN; k0 += KT) {
#pragma unroll
        for (int l = 0; l < 4; l++)
            *(float4*)&Bs[brow + 8 * l][bcol] = pb[l];
#pragma unroll
        for (int l = 0; l < 2; l++) {
            int kk = akk + 16 * l;
            As[0 * KT + kk][aii] = pa0[l];
            if (NMAT > 1) As[1 * KT + kk][aii] = pa1[l];
            if (NMAT > 2) As[2 * KT + kk][aii] = pa2[l];
        }
        __syncthreads();
        int kn = k0 + KT;
        if (kn < DIN) {
#pragma unroll
            for (int l = 0; l < 4; l++)
                pb[l] = *(const float4*)&Bmat[(kn + brow + 8 * l) * 128 + bcol];
#pragma unroll
            for (int l = 0; l < 2; l++) {
                int kk = kn + akk + 16 * l;
                pa0[l] = AT0[kk * DIN + i0 + aii];
                if (NMAT > 1) pa1[l] = AT1[kk * DIN + i0 + aii];
                if (NMAT > 2) pa2[l] = AT2[kk * DIN + i0 + aii];
            }
        }
#pragma unroll
        for (int kk = 0; kk < KT; kk++) {
            ull b[4];
            b[0] = *(const ull*)&Bs[kk][tj * 8 + 0];
            b[1] = *(const ull*)&Bs[kk][tj * 8 + 2];
            b[2] = *(const ull*)&Bs[kk][tj * 8 + 4];
            b[3] = *(const ull*)&Bs[kk][tj * 8 + 6];
            {
                ull av = dup2(As[0 * KT + kk][ti]);
#pragma unroll
                for (int j = 0; j < 4; j++)
                    asm("fma.rn.f32x2 %0, %1, %2, %0;" : "+l"(a0[j]) : "l"(av), "l"(b[j]));
            }
            if (NMAT > 1) {
                ull av = dup2(As[1 * KT + kk][ti]);
#pragma unroll
                for (int j = 0; j < 4; j++)
                    asm("fma.rn.f32x2 %0, %1, %2, %0;" : "+l"(a1[j]) : "l"(av), "l"(b[j]));
            }
            if (NMAT > 2) {
                ull av = dup2(As[2 * KT + kk][ti]);
#pragma unroll
                for (int j = 0; j < 4; j++)
                    asm("fma.rn.f32x2 %0, %1, %2, %0;" : "+l"(a2[j]) : "l"(av), "l"(b[j]));
            }
        }
        __syncthreads();
    }
}

// ---- gruA: z = sig(WXz + Uz@W + bz), r = sig(WXr + Ur@W + br), rW = r*W ------
__device__ __forceinline__ void dev_gruA(int t, int bx,
                                         const float* __restrict__ bz,
                                         const float* __restrict__ br,
                                         char* sm) {
    int i0 = bx * 16;
    ull a0[4] = {0, 0, 0, 0}, a1[4] = {0, 0, 0, 0};
    gemm16<2>(g_WT + 1 * MSQ, g_WT + 3 * MSQ, (const float*)0,
              g_Wn + t * MAT, i0, a0, a1, a0, sm);
    int ti = threadIdx.x & 15, tj = threadIdx.x >> 4;
    int row = i0 + ti, col = tj * 8;
    const float* WXz = g_WX + (0 * TT + t) * MAT;
    const float* WXr = g_WX + (1 * TT + t) * MAT;
    const float* Wt  = g_Wn + t * MAT;
#pragma unroll
    for (int j = 0; j < 4; j++) {
        int o = row * DOUT + col + 2 * j;
        float2 az = upk(a0[j]), ar = upk(a1[j]);
        float2 xz = *(const float2*)&WXz[o];
        float2 xr = *(const float2*)&WXr[o];
        float2 vz = *(const float2*)&bz[o];
        float2 vr = *(const float2*)&br[o];
        float2 wv = *(const float2*)&Wt[o];
        float2 z2, rw2;
        z2.x = sigmoidf_(az.x + xz.x + vz.x);
        z2.y = sigmoidf_(az.y + xz.y + vz.y);
        rw2.x = sigmoidf_(ar.x + xr.x + vr.x) * wv.x;
        rw2.y = sigmoidf_(ar.y + xr.y + vr.y) * wv.y;
        *(float2*)&g_z[o] = z2;
        *(float2*)&g_rW[o] = rw2;
    }
}

// ---- gruB: h = tanh(WXh + Uh@rW + bh); Wn_{t+1} = W + z*(h - W) --------------
__global__ void gruB_kernel(int t, const float* __restrict__ bh) {
    __shared__ __align__(16) char sm[KT * 128 * 4 + KT * 16 * 4];
    int i0 = blockIdx.x * 16;
    ull a0[4] = {0, 0, 0, 0};
    gemm16<1>(g_WT + 5 * MSQ, (const float*)0, (const float*)0,
              g_rW, i0, a0, a0, a0, sm);
    int ti = threadIdx.x & 15, tj = threadIdx.x >> 4;
    int row = i0 + ti, col = tj * 8;
    const float* WXh = g_WX + (2 * TT + t) * MAT;
    const float* Wt  = g_Wn + t * MAT;
    float* Wnx = g_Wn + (t + 1) * MAT;
#pragma unroll
    for (int j = 0; j < 4; j++) {
        int o = row * DOUT + col + 2 * j;
        float2 ah = upk(a0[j]);
        float2 xh = *(const float2*)&WXh[o];
        float2 vh = *(const float2*)&bh[o];
        float2 wv = *(const float2*)&Wt[o];
        float2 z2 = *(const float2*)&g_z[o];
        float hx = tanhf(ah.x + xh.x + vh.x);
        float hy = tanhf(ah.y + xh.y + vh.y);
        float2 wn;
        wn.x = wv.x + z2.x * (hx - wv.x);
        wn.y = wv.y + z2.y * (hy - wv.y);
        *(float2*)&Wnx[o] = wn;
    }
}

// ================= wxfill: WX GEMMs (64 blocks) | CSR fill (10000) ============
__global__ void wxfill_kernel(const int* __restrict__ ei, const float* __restrict__ w) {
    int b = blockIdx.x;
    if (b < 64) {
        __shared__ __align__(16) char sm[KT * 128 * 4 + 3 * KT * 16 * 4];
        int t = b >> 4, i0 = (b & 15) * 16;
        ull a0[4] = {0, 0, 0, 0}, a1[4] = {0, 0, 0, 0}, a2[4] = {0, 0, 0, 0};
        gemm16<3>(g_WT + 0 * MSQ, g_WT + 2 * MSQ, g_WT + 4 * MSQ,
                  g_xt + t * MAT, i0, a0, a1, a2, sm);
        int ti = threadIdx.x & 15, tj = threadIdx.x >> 4;
        int base = (i0 + ti) * DOUT + tj * 8;
#pragma unroll
        for (int j = 0; j < 4; j++) {
            *(ull*)&g_WX[(0 * TT + t) * MAT + base + 2 * j] = a0[j];
            *(ull*)&g_WX[(1 * TT + t) * MAT + base + 2 * j] = a1[j];
            *(ull*)&g_WX[(2 * TT + t) * MAT + base + 2 * j] = a2[j];
        }
    } else {
        int idx = b - 64;
        int t = idx / 2500;
        int e = (idx % 2500) * 256 + threadIdx.x;
        const int* dst = ei + (size_t)t * 2 * EE;
        const int* src = dst + EE;
        int d = dst[e];
        int pos = atomicAdd(&g_cur[t * NN + d], 1);
        g_csr[(size_t)t * EE + pos] = make_int2(src[e], __float_as_int(w[(size_t)t * EE + e]));
    }
}

// ================= sgemm / gather bodies =====================================
#define BM 128
#define BN 128
#define BK 32
#define SGB 157

__device__ __forceinline__ void dev_sgemm(int t, int bx, const float* __restrict__ embs,
                                          char* sm) {
    float (*As)[BM + 1] = (float(*)[BM + 1])sm;
    float (*Bs)[BN]     = (float(*)[BN])(sm + BK * (BM + 1) * 4);
    const float* A = embs + (size_t)t * NN * DIN;
    const float* B = g_Wn + (t + 1) * MAT;
    float* C = g_y + (size_t)t * NN * DOUT;

    int tid = threadIdx.x;           // 256
    int bm = bx * BM;
    int tx = tid & 15;
    int ty = tid >> 4;
    int ar = tid >> 3;
    int ac = (tid & 7) * 4;

    ull acc[8][4];
#pragma unroll
    for (int m = 0; m < 8; m++)
#pragma unroll
        for (int j = 0; j < 4; j++) acc[m][j] = 0ull;

    float4 pa[4], pb[4];
#pragma unroll
    for (int pass = 0; pass < 4; pass++) {
        int gr = bm + pass * 32 + ar;
        pa[pass] = (gr < NN) ? *(const float4*)&A[(size_t)gr * DIN + ac]
                             : make_float4(0.f, 0.f, 0.f, 0.f);
        int q = pass * 256 + tid;
        pb[pass] = *(const float4*)&B[(q >> 5) * BN + (q & 31) * 4];
    }

    for (int k0 = 0; k0 < DIN; k0 += BK) {
#pragma unroll
        for (int pass = 0; pass < 4; pass++) {
            int r = pass * 32 + ar;
            As[ac + 0][r] = pa[pass].x;
            As[ac + 1][r] = pa[pass].y;
            As[ac + 2][r] = pa[pass].z;
            As[ac + 3][r] = pa[pass].w;
            int q = pass * 256 + tid;
            *(float4*)&Bs[q >> 5][(q & 31) * 4] = pb[pass];
        }
        __syncthreads();
        int kn = k0 + BK;
        if (kn < DIN) {
#pragma unroll
            for (int pass = 0; pass < 4; pass++) {
                int gr = bm + pass * 32 + ar;
                pa[pass] = (gr < NN) ? *(const float4*)&A[(size_t)gr * DIN + kn + ac]
                                     : make_float4(0.f, 0.f, 0.f, 0.f);
                int q = pass * 256 + tid;
                pb[pass] = *(const float4*)&B[(kn + (q >> 5)) * BN + (q & 31) * 4];
            }
        }
#pragma unroll
        for (int kk = 0; kk < BK; kk++) {
            ull b2[4];
#pragma unroll
            for (int j = 0; j < 4; j++)
                b2[j] = *(const ull*)&Bs[kk][tx * 2 + 32 * j];
#pragma unroll
            for (int m = 0; m < 8; m++) {
                ull a2 = dup2(As[kk][ty * 8 + m]);
#pragma unroll
                for (int j = 0; j < 4; j++)
                    asm("fma.rn.f32x2 %0, %1, %2, %0;"
                        : "+l"(acc[m][j]) : "l"(a2), "l"(b2[j]));
            }
        }
        __syncthreads();
    }
#pragma unroll
    for (int m = 0; m < 8; m++) {
        int gr = bm + ty * 8 + m;
        if (gr < NN) {
#pragma unroll
            for (int j = 0; j < 4; j++)
                *(ull*)&C[(size_t)gr * DOUT + tx * 2 + 32 * j] = acc[m][j];
        }
    }
}

__device__ __forceinline__ void dev_gather(int t, int bx, float* __restrict__ out) {
    int node = bx * 8 + (threadIdx.x >> 5);
    int lane = threadIdx.x & 31;
    const int* off = g_off + t * (NN + 1);
    const int2* csr = g_csr + (size_t)t * EE;
    const float* y = g_y + (size_t)t * NN * DOUT;
    int beg = off[node], end = off[node + 1];
    float4 acc = make_float4(0.f, 0.f, 0.f, 0.f);
    int e = beg;
    for (; e + 4 <= end; e += 4) {
        int2 c0 = csr[e + 0], c1 = csr[e + 1], c2 = csr[e + 2], c3 = csr[e + 3];
        float4 v0 = *(const float4*)&y[(size_t)c0.x * DOUT + lane * 4];
        float4 v1 = *(const float4*)&y[(size_t)c1.x * DOUT + lane * 4];
        float4 v2 = *(const float4*)&y[(size_t)c2.x * DOUT + lane * 4];
        float4 v3 = *(const float4*)&y[(size_t)c3.x * DOUT + lane * 4];
        float w0 = __int_as_float(c0.y), w1 = __int_as_float(c1.y);
        float w2 = __int_as_float(c2.y), w3 = __int_as_float(c3.y);
        acc.x += w0 * v0.x + w1 * v1.x + w2 * v2.x + w3 * v3.x;
        acc.y += w0 * v0.y + w1 * v1.y + w2 * v2.y + w3 * v3.y;
        acc.z += w0 * v0.z + w1 * v1.z + w2 * v2.z + w3 * v3.z;
        acc.w += w0 * v0.w + w1 * v1.w + w2 * v2.w + w3 * v3.w;
    }
    for (; e < end; e++) {
        int2 c0 = csr[e];
        float w0 = __int_as_float(c0.y);
        float4 v0 = *(const float4*)&y[(size_t)c0.x * DOUT + lane * 4];
        acc.x += w0 * v0.x; acc.y += w0 * v0.y; acc.z += w0 * v0.z; acc.w += w0 * v0.w;
    }
    acc.x = (acc.x >= 0.f) ? acc.x : SLOPE * acc.x;
    acc.y = (acc.y >= 0.f) ? acc.y : SLOPE * acc.y;
    acc.z = (acc.z >= 0.f) ? acc.z : SLOPE * acc.z;
    acc.w = (acc.w >= 0.f) ? acc.w : SLOPE * acc.w;
    *(float4*)&out[((size_t)t * NN + node) * DOUT + lane * 4] = acc;
}

// ================= pipe: [gruA(t_sg+1)] | sgemm(t_sg) | [gather(t_ga)] ========
__global__ void pipe_kernel(int t_sg, int t_ga, int ngru,
                            const float* __restrict__ embs,
                            const float* __restrict__ bz, const float* __restrict__ br,
                            float* __restrict__ out) {
    __shared__ __align__(16) char sm[BK * (BM + 1) * 4 + BK * BN * 4];
    int b = blockIdx.x;
    if (b < ngru)                 dev_gruA(t_sg + 1, b, bz, br, sm);
    else if (b < ngru + SGB)      dev_sgemm(t_sg, b - ngru, embs, sm);
    else                          dev_gather(t_ga, b - ngru - SGB, out);
}

__global__ void gruA0_kernel(const float* __restrict__ bz, const float* __restrict__ br) {
    __shared__ __align__(16) char sm[KT * 128 * 4 + 2 * KT * 16 * 4];
    dev_gruA(0, blockIdx.x, bz, br, sm);
}

__global__ void gather_only_kernel(int t, float* __restrict__ out) {
    dev_gather(t, blockIdx.x, out);
}

// ---------------- launcher ----------------
extern "C" void kernel_launch(void* const* d_in, const int* in_sizes, int n_in,
                              void* d_out, int out_size) {
    const float* node_embs  = (const float*)d_in[0];
    const int*   edge_index = (const int*)d_in[1];
    const float* edge_w     = (const float*)d_in[2];
    const float* mask       = (const float*)d_in[3];
    const float* p          = (const float*)d_in[4];
    const float* Wz         = (const float*)d_in[5];
    const float* Uz         = (const float*)d_in[6];
    const float* bz         = (const float*)d_in[7];
    const float* Wr         = (const float*)d_in[8];
    const float* Ur         = (const float*)d_in[9];
    const float* br         = (const float*)d_in[10];
    const float* Wh         = (const float*)d_in[11];
    const float* Uh         = (const float*)d_in[12];
    const float* bh         = (const float*)d_in[13];
    const float* W0         = (const float*)d_in[14];
    float* out = (float*)d_out;

    front_kernel<<<FB_TOTAL, 256>>>(node_embs, p, mask, edge_index,
                                    Wz, Uz, Wr, Ur, Wh, Uh, W0);
    mid1_kernel<<<36, 1024>>>();
    mid2_kernel<<<4, 1024>>>(node_embs);
    wxfill_kernel<<<64 + 10000, 256>>>(edge_index, edge_w);

    gruA0_kernel<<<16, 256>>>(bz, br);
    gruB_kernel<<<16, 256>>>(0, bh);
    // P1: sgemm(0) + gruA(1)
    pipe_kernel<<<16 + SGB, 256>>>(0, 0, 16, node_embs, bz, br, out);
    gruB_kernel<<<16, 256>>>(1, bh);
    // P2: sgemm(1) + gather(0) + gruA(2)
    pipe_kernel<<<16 + SGB + 2500, 256>>>(1, 0, 16, node_embs, bz, br, out);
    gruB_kernel<<<16, 256>>>(2, bh);
    // P3: sgemm(2) + gather(1) + gruA(3)
    pipe_kernel<<<16 + SGB + 2500, 256>>>(2, 1, 16, node_embs, bz, br, out);
    gruB_kernel<<<16, 256>>>(3, bh);
    // P4: sgemm(3) + gather(2)
    pipe_kernel<<<SGB + 2500, 256>>>(3, 2, 0, node_embs, bz, br, out);
    gather_only_kernel<<<2500, 256>>>(3, out);
}

// round 5
// speedup vs baseline: 1.5692x; 1.2933x over previous
#include <cuda_runtime.h>
#include <cuda_fp16.h>

#define TT   4
#define NN   20000
#define EE   640000
#define DIN  256
#define DOUT 128
#define MAT  (DIN * DOUT)      // 32768
#define MSQ  (DIN * DIN)       // 65536
#define SLOPE 0.22916666666666666f

typedef unsigned long long ull;

// ---------------- scratch (__device__ globals; no allocation) ----------------
__device__ float g_scores[TT * NN];
__device__ float g_xt[TT * MAT];             // per-t [256][128]
__device__ float g_Wn[(TT + 1) * MAT];       // W0 + evolved weights
__device__ float g_WT[6 * MSQ];              // transposed Wz,Uz,Wr,Ur,Wh,Uh
__device__ float g_WX[3 * TT * MAT];         // Wz@xt, Wr@xt, Wh@xt per t
__device__ float g_z[MAT];
__device__ float g_rW[MAT];
__device__ __half g_y[(size_t)TT * NN * DOUT];   // fp16 y (halves gather traffic)
__device__ int   g_deg[TT * NN];
__device__ int   g_off[TT * (NN + 1)];
__device__ int   g_cur[TT * NN];
__device__ int2  g_csr[(size_t)TT * EE];
__device__ int   g_hist[TT * 4096];

// ---------------- helpers ----------------
__device__ __forceinline__ unsigned ord_of(float f) {
    unsigned b = __float_as_uint(f);
    return b ^ ((b & 0x80000000u) ? 0xFFFFFFFFu : 0x80000000u);
}
__device__ __forceinline__ float sigmoidf_(float x) {
    return 1.0f / (1.0f + expf(-x));
}
__device__ __forceinline__ float2 upk(ull v) {
    float2 r;
    asm("mov.b64 {%0, %1}, %2;" : "=f"(r.x), "=f"(r.y) : "l"(v));
    return r;
}
__device__ __forceinline__ ull dup2(float a) {
    ull r;
    asm("mov.b64 %0, {%1, %1};" : "=l"(r) : "f"(a));
    return r;
}

// ================= L1: front = scores | deg | prep-transpose | hist-zero =====
#define FB_SCORES 10000
#define FB_DEG    10000
#define FB_PREP   1664
#define FB_HZERO  64
#define FB_TOTAL  (FB_SCORES + FB_DEG + FB_PREP + FB_HZERO)

__global__ void front_kernel(const float* __restrict__ embs,
                             const float* __restrict__ p,
                             const float* __restrict__ mask,
                             const int* __restrict__ ei,
                             const float* __restrict__ Wz, const float* __restrict__ Uz,
                             const float* __restrict__ Wr, const float* __restrict__ Ur,
                             const float* __restrict__ Wh, const float* __restrict__ Uh,
                             const float* __restrict__ W0) {
    int b = blockIdx.x;
    int tid = threadIdx.x;
    if (b < FB_SCORES) {
        __shared__ float sp[DIN];
        sp[tid] = p[tid];
        __syncthreads();
        int t = b / 2500;
        int warp = tid >> 5, lane = tid & 31;
        int n = (b % 2500) * 8 + warp;
        const float* xr = embs + ((size_t)t * NN + n) * DIN;
        float4 x0 = *(const float4*)&xr[lane * 4];
        float4 x1 = *(const float4*)&xr[128 + lane * 4];
        float4 p0 = *(const float4*)&sp[lane * 4];
        float4 p1 = *(const float4*)&sp[128 + lane * 4];
        float s = x0.x * p0.x + x0.y * p0.y + x0.z * p0.z + x0.w * p0.w
                + x1.x * p1.x + x1.y * p1.y + x1.z * p1.z + x1.w * p1.w;
        float q = p0.x * p0.x + p0.y * p0.y + p0.z * p0.z + p0.w * p0.w
                + p1.x * p1.x + p1.y * p1.y + p1.z * p1.z + p1.w * p1.w;
#pragma unroll
        for (int o = 16; o > 0; o >>= 1) {
            s += __shfl_down_sync(0xFFFFFFFFu, s, o);
            q += __shfl_down_sync(0xFFFFFFFFu, q, o);
        }
        if (lane == 0) g_scores[t * NN + n] = s * rsqrtf(q) + mask[t * NN + n];
    } else if (b < FB_SCORES + FB_DEG) {
        int idx = b - FB_SCORES;
        int t = idx / 2500;
        int e = (idx % 2500) * 256 + tid;
        const int* dst = ei + (size_t)t * 2 * EE;
        atomicAdd(&g_deg[t * NN + dst[e]], 1);
    } else if (b < FB_SCORES + FB_DEG + FB_PREP) {
        int idx = (b - FB_SCORES - FB_DEG) * 256 + tid;
        const float* srcs[6] = {Wz, Uz, Wr, Ur, Wh, Uh};
        if (idx < 6 * MSQ) {
            int m = idx >> 16;
            int e = idx & 0xFFFF;
            int k = e >> 8, i = e & 255;
            g_WT[idx] = srcs[m][i * DIN + k];
        } else {
            int e = idx - 6 * MSQ;
            g_Wn[e] = W0[e];
        }
    } else {
        int i = (b - FB_SCORES - FB_DEG - FB_PREP) * 256 + tid;
        if (i < TT * 4096) g_hist[i] = 0;
    }
}

// ================= L2: mid1 = hist(32 blocks) | scan(4 blocks) ================
__device__ void do_scan(int t) {
    __shared__ int part[1024];
    int tid = threadIdx.x;
    int* deg = g_deg + t * NN;
    int* off = g_off + t * (NN + 1);
    int* cur = g_cur + t * NN;
    int base = tid * 20;
    int loc[20];
    int sum = 0;
#pragma unroll
    for (int i = 0; i < 20; i++) {
        int n = base + i;
        int d = (n < NN) ? deg[n] : 0;
        if (n < NN) deg[n] = 0;     // re-zero for graph replay
        loc[i] = sum;
        sum += d;
    }
    part[tid] = sum;
    __syncthreads();
    for (int o = 1; o < 1024; o <<= 1) {
        int v = (tid >= o) ? part[tid - o] : 0;
        __syncthreads();
        part[tid] += v;
        __syncthreads();
    }
    int myoff = tid ? part[tid - 1] : 0;
#pragma unroll
    for (int i = 0; i < 20; i++) {
        int n = base + i;
        if (n <= NN) {
            int o = myoff + loc[i];
            off[n] = o;
            if (n < NN) cur[n] = o;
        }
    }
}

__global__ void mid1_kernel() {
    int b = blockIdx.x;
    int tid = threadIdx.x;   // 1024
    if (b < 32) {
        __shared__ int h[4096];
        int t = b >> 3, chunk = b & 7;
#pragma unroll
        for (int j = 0; j < 4; j++) h[tid + j * 1024] = 0;
        __syncthreads();
        const float* scores = g_scores + t * NN;
        int base = chunk * 2500;
        for (int n = base + tid; n < base + 2500; n += 1024)
            atomicAdd(&h[ord_of(scores[n]) >> 20], 1);
        __syncthreads();
#pragma unroll
        for (int j = 0; j < 4; j++) {
            int bin = tid + j * 1024;
            int v = h[bin];
            if (v) atomicAdd(&g_hist[t * 4096 + bin], v);
        }
    } else {
        do_scan(b - 32);
    }
}

// ================= L3: mid2 = per-t select + xt build ========================
__global__ void mid2_kernel(const float* __restrict__ embs) {
    int t = blockIdx.x;
    int tid = threadIdx.x;   // 1024
    __shared__ int part[1024];
    __shared__ int sB, sAbove;
    __shared__ unsigned cnt_gt, cnt_cand;
    __shared__ unsigned sel_ord[DOUT];
    __shared__ int sel_idx[DOUT];
    __shared__ unsigned cand_ord[512];
    __shared__ int cand_idx[512];
    __shared__ int sh_idx[DOUT];
    __shared__ float sh_tanh[DOUT];

    const float* scores = g_scores + t * NN;
    const int* hist = g_hist + t * 4096;

    int cnt[4];
    int s = 0;
#pragma unroll
    for (int j = 0; j < 4; j++) {
        int bin = 4095 - (tid * 4 + j);
        cnt[j] = hist[bin];
        s += cnt[j];
    }
    part[tid] = s;
    if (tid == 0) { cnt_gt = 0; cnt_cand = 0; }
    __syncthreads();
    for (int o = 1; o < 1024; o <<= 1) {
        int v = (tid >= o) ? part[tid - o] : 0;
        __syncthreads();
        part[tid] += v;
        __syncthreads();
    }
    int c = tid ? part[tid - 1] : 0;
#pragma unroll
    for (int j = 0; j < 4; j++) {
        int bin = 4095 - (tid * 4 + j);
        if (c < DOUT && c + cnt[j] >= DOUT) { sB = bin; sAbove = c; }
        c += cnt[j];
    }
    __syncthreads();
    int B = sB, above = sAbove, kneed = DOUT - above;

    for (int n = tid; n < NN; n += 1024) {
        unsigned ord = ord_of(scores[n]);
        int bucket = ord >> 20;
        if (bucket > B) {
            unsigned pos = atomicAdd(&cnt_gt, 1u);
            sel_ord[pos] = ord; sel_idx[pos] = n;
        } else if (bucket == B) {
            unsigned pos = atomicAdd(&cnt_cand, 1u);
            if (pos < 512) { cand_ord[pos] = ord; cand_idx[pos] = n; }
        }
    }
    __syncthreads();
    int nc = (int)cnt_cand; if (nc > 512) nc = 512;
    for (int ci = tid; ci < nc; ci += 1024) {
        unsigned mo = cand_ord[ci];
        int mi = cand_idx[ci];
        int r = 0;
        for (int j = 0; j < nc; j++) {
            unsigned o = cand_ord[j];
            r += (o > mo) || (o == mo && cand_idx[j] < mi);
        }
        if (r < kneed) { sel_ord[above + r] = mo; sel_idx[above + r] = mi; }
    }
    __syncthreads();
    if (tid < DOUT) {
        unsigned mo = sel_ord[tid];
        int mi = sel_idx[tid];
        int r = 0;
#pragma unroll 4
        for (int i = 0; i < DOUT; i++) {
            unsigned o = sel_ord[i];
            r += (o > mo) || (o == mo && sel_idx[i] < mi);
        }
        sh_idx[r] = mi;
        sh_tanh[r] = tanhf(scores[mi]);
    }
    __syncthreads();
    float* xt = g_xt + t * MAT;
    for (int e = tid; e < MAT; e += 1024) {
        int j = e >> 8;
        int d = e & 255;
        xt[d * DOUT + j] = embs[((size_t)t * NN + sh_idx[j]) * DIN + d] * sh_tanh[j];
    }
}

// ================= small GEMM: 16x128 tile, K=256, up to 3 A-mats sharing B ===
#define KT 32
template <int NMAT>
__device__ __forceinline__ void gemm16(const float* __restrict__ AT0,
                                       const float* __restrict__ AT1,
                                       const float* __restrict__ AT2,
                                       const float* __restrict__ Bmat,
                                       int i0, ull a0[4], ull a1[4], ull a2[4],
                                       char* sm) {
    float (*Bs)[128] = (float(*)[128])sm;
    float (*As)[16]  = (float(*)[16])(sm + KT * 128 * 4);
    int tid = threadIdx.x;           // 256
    int ti = tid & 15, tj = tid >> 4;
    int brow = tid >> 5, bcol = (tid & 31) * 4;
    int akk = tid >> 4, aii = tid & 15;

    float4 pb[4];
    float pa0[2], pa1[2], pa2[2];
#pragma unroll
    for (int l = 0; l < 4; l++)
        pb[l] = *(const float4*)&Bmat[(brow + 8 * l) * 128 + bcol];
#pragma unroll
    for (int l = 0; l < 2; l++) {
        int kk = akk + 16 * l;
        pa0[l] = AT0[kk * DIN + i0 + aii];
        if (NMAT > 1) pa1[l] = AT1[kk * DIN + i0 + aii];
        if (NMAT > 2) pa2[l] = AT2[kk * DIN + i0 + aii];
    }
    for (int k0 = 0; k0 < DIN; k0 += KT) {
#pragma unroll
        for (int l = 0; l < 4; l++)
            *(float4*)&Bs[brow + 8 * l][bcol] = pb[l];
#pragma unroll
        for (int l = 0; l < 2; l++) {
            int kk = akk + 16 * l;
            As[0 * KT + kk][aii] = pa0[l];
            if (NMAT > 1) As[1 * KT + kk][aii] = pa1[l];
            if (NMAT > 2) As[2 * KT + kk][aii] = pa2[l];
        }
        __syncthreads();
        int kn = k0 + KT;
        if (kn < DIN) {
#pragma unroll
            for (int l = 0; l < 4; l++)
                pb[l] = *(const float4*)&Bmat[(kn + brow + 8 * l) * 128 + bcol];
#pragma unroll
            for (int l = 0; l < 2; l++) {
                int kk = kn + akk + 16 * l;
                pa0[l] = AT0[kk * DIN + i0 + aii];
                if (NMAT > 1) pa1[l] = AT1[kk * DIN + i0 + aii];
                if (NMAT > 2) pa2[l] = AT2[kk * DIN + i0 + aii];
            }
        }
#pragma unroll
        for (int kk = 0; kk < KT; kk++) {
            ull b[4];
            b[0] = *(const ull*)&Bs[kk][tj * 8 + 0];
            b[1] = *(const ull*)&Bs[kk][tj * 8 + 2];
            b[2] = *(const ull*)&Bs[kk][tj * 8 + 4];
            b[3] = *(const ull*)&Bs[kk][tj * 8 + 6];
            {
                ull av = dup2(As[0 * KT + kk][ti]);
#pragma unroll
                for (int j = 0; j < 4; j++)
                    asm("fma.rn.f32x2 %0, %1, %2, %0;" : "+l"(a0[j]) : "l"(av), "l"(b[j]));
            }
            if (NMAT > 1) {
                ull av = dup2(As[1 * KT + kk][ti]);
#pragma unroll
                for (int j = 0; j < 4; j++)
                    asm("fma.rn.f32x2 %0, %1, %2, %0;" : "+l"(a1[j]) : "l"(av), "l"(b[j]));
            }
            if (NMAT > 2) {
                ull av = dup2(As[2 * KT + kk][ti]);
#pragma unroll
                for (int j = 0; j < 4; j++)
                    asm("fma.rn.f32x2 %0, %1, %2, %0;" : "+l"(a2[j]) : "l"(av), "l"(b[j]));
            }
        }
        __syncthreads();
    }
}

// ---- gruA: z = sig(WXz + Uz@W + bz), r = sig(WXr + Ur@W + br), rW = r*W ------
__device__ __forceinline__ void dev_gruA(int t, int bx,
                                         const float* __restrict__ bz,
                                         const float* __restrict__ br,
                                         char* sm) {
    int i0 = bx * 16;
    ull a0[4] = {0, 0, 0, 0}, a1[4] = {0, 0, 0, 0};
    gemm16<2>(g_WT + 1 * MSQ, g_WT + 3 * MSQ, (const float*)0,
              g_Wn + t * MAT, i0, a0, a1, a0, sm);
    int ti = threadIdx.x & 15, tj = threadIdx.x >> 4;
    int row = i0 + ti, col = tj * 8;
    const float* WXz = g_WX + (0 * TT + t) * MAT;
    const float* WXr = g_WX + (1 * TT + t) * MAT;
    const float* Wt  = g_Wn + t * MAT;
#pragma unroll
    for (int j = 0; j < 4; j++) {
        int o = row * DOUT + col + 2 * j;
        float2 az = upk(a0[j]), ar = upk(a1[j]);
        float2 xz = *(const float2*)&WXz[o];
        float2 xr = *(const float2*)&WXr[o];
        float2 vz = *(const float2*)&bz[o];
        float2 vr = *(const float2*)&br[o];
        float2 wv = *(const float2*)&Wt[o];
        float2 z2, rw2;
        z2.x = sigmoidf_(az.x + xz.x + vz.x);
        z2.y = sigmoidf_(az.y + xz.y + vz.y);
        rw2.x = sigmoidf_(ar.x + xr.x + vr.x) * wv.x;
        rw2.y = sigmoidf_(ar.y + xr.y + vr.y) * wv.y;
        *(float2*)&g_z[o] = z2;
        *(float2*)&g_rW[o] = rw2;
    }
}

// ---- gruB: h = tanh(WXh + Uh@rW + bh); Wn_{t+1} = W + z*(h - W) --------------
__global__ void gruB_kernel(int t, const float* __restrict__ bh) {
    __shared__ __align__(16) char sm[KT * 128 * 4 + KT * 16 * 4];
    int i0 = blockIdx.x * 16;
    ull a0[4] = {0, 0, 0, 0};
    gemm16<1>(g_WT + 5 * MSQ, (const float*)0, (const float*)0,
              g_rW, i0, a0, a0, a0, sm);
    int ti = threadIdx.x & 15, tj = threadIdx.x >> 4;
    int row = i0 + ti, col = tj * 8;
    const float* WXh = g_WX + (2 * TT + t) * MAT;
    const float* Wt  = g_Wn + t * MAT;
    float* Wnx = g_Wn + (t + 1) * MAT;
#pragma unroll
    for (int j = 0; j < 4; j++) {
        int o = row * DOUT + col + 2 * j;
        float2 ah = upk(a0[j]);
        float2 xh = *(const float2*)&WXh[o];
        float2 vh = *(const float2*)&bh[o];
        float2 wv = *(const float2*)&Wt[o];
        float2 z2 = *(const float2*)&g_z[o];
        float hx = tanhf(ah.x + xh.x + vh.x);
        float hy = tanhf(ah.y + xh.y + vh.y);
        float2 wn;
        wn.x = wv.x + z2.x * (hx - wv.x);
        wn.y = wv.y + z2.y * (hy - wv.y);
        *(float2*)&Wnx[o] = wn;
    }
}

// ---- CSR fill body (2500 blocks per t) ---------------------------------------
__device__ __forceinline__ void dev_fill(int t, int bx,
                                         const int* __restrict__ ei,
                                         const float* __restrict__ w) {
    int e = bx * 256 + threadIdx.x;
    const int* dst = ei + (size_t)t * 2 * EE;
    const int* src = dst + EE;
    int d = dst[e];
    int pos = atomicAdd(&g_cur[t * NN + d], 1);
    g_csr[(size_t)t * EE + pos] = make_int2(src[e], __float_as_int(w[(size_t)t * EE + e]));
}

// ================= wxfill: WX GEMMs (64 blocks) | fill(0) (2500) ==============
__global__ void wxfill_kernel(const int* __restrict__ ei, const float* __restrict__ w) {
    int b = blockIdx.x;
    if (b < 64) {
        __shared__ __align__(16) char sm[KT * 128 * 4 + 3 * KT * 16 * 4];
        int t = b >> 4, i0 = (b & 15) * 16;
        ull a0[4] = {0, 0, 0, 0}, a1[4] = {0, 0, 0, 0}, a2[4] = {0, 0, 0, 0};
        gemm16<3>(g_WT + 0 * MSQ, g_WT + 2 * MSQ, g_WT + 4 * MSQ,
                  g_xt + t * MAT, i0, a0, a1, a2, sm);
        int ti = threadIdx.x & 15, tj = threadIdx.x >> 4;
        int base = (i0 + ti) * DOUT + tj * 8;
#pragma unroll
        for (int j = 0; j < 4; j++) {
            *(ull*)&g_WX[(0 * TT + t) * MAT + base + 2 * j] = a0[j];
            *(ull*)&g_WX[(1 * TT + t) * MAT + base + 2 * j] = a1[j];
            *(ull*)&g_WX[(2 * TT + t) * MAT + base + 2 * j] = a2[j];
        }
    } else {
        dev_fill(0, b - 64, ei, w);
    }
}

// ================= sgemm / gather bodies =====================================
#define BM 128
#define BN 128
#define BK 32
#define SGB 157

__device__ __forceinline__ void dev_sgemm(int t, int bx, const float* __restrict__ embs,
                                          char* sm) {
    float (*As)[BM + 1] = (float(*)[BM + 1])sm;
    float (*Bs)[BN]     = (float(*)[BN])(sm + BK * (BM + 1) * 4);
    const float* A = embs + (size_t)t * NN * DIN;
    const float* B = g_Wn + (t + 1) * MAT;
    __half* C = g_y + (size_t)t * NN * DOUT;

    int tid = threadIdx.x;           // 256
    int bm = bx * BM;
    int tx = tid & 15;
    int ty = tid >> 4;
    int ar = tid >> 3;
    int ac = (tid & 7) * 4;

    ull acc[8][4];
#pragma unroll
    for (int m = 0; m < 8; m++)
#pragma unroll
        for (int j = 0; j < 4; j++) acc[m][j] = 0ull;

    float4 pa[4], pb[4];
#pragma unroll
    for (int pass = 0; pass < 4; pass++) {
        int gr = bm + pass * 32 + ar;
        pa[pass] = (gr < NN) ? *(const float4*)&A[(size_t)gr * DIN + ac]
                             : make_float4(0.f, 0.f, 0.f, 0.f);
        int q = pass * 256 + tid;
        pb[pass] = *(const float4*)&B[(q >> 5) * BN + (q & 31) * 4];
    }

    for (int k0 = 0; k0 < DIN; k0 += BK) {
#pragma unroll
        for (int pass = 0; pass < 4; pass++) {
            int r = pass * 32 + ar;
            As[ac + 0][r] = pa[pass].x;
            As[ac + 1][r] = pa[pass].y;
            As[ac + 2][r] = pa[pass].z;
            As[ac + 3][r] = pa[pass].w;
            int q = pass * 256 + tid;
            *(float4*)&Bs[q >> 5][(q & 31) * 4] = pb[pass];
        }
        __syncthreads();
        int kn = k0 + BK;
        if (kn < DIN) {
#pragma unroll
            for (int pass = 0; pass < 4; pass++) {
                int gr = bm + pass * 32 + ar;
                pa[pass] = (gr < NN) ? *(const float4*)&A[(size_t)gr * DIN + kn + ac]
                                     : make_float4(0.f, 0.f, 0.f, 0.f);
                int q = pass * 256 + tid;
                pb[pass] = *(const float4*)&B[(kn + (q >> 5)) * BN + (q & 31) * 4];
            }
        }
#pragma unroll
        for (int kk = 0; kk < BK; kk++) {
            ull b2[4];
#pragma unroll
            for (int j = 0; j < 4; j++)
                b2[j] = *(const ull*)&Bs[kk][tx * 2 + 32 * j];
#pragma unroll
            for (int m = 0; m < 8; m++) {
                ull a2 = dup2(As[kk][ty * 8 + m]);
#pragma unroll
                for (int j = 0; j < 4; j++)
                    asm("fma.rn.f32x2 %0, %1, %2, %0;"
                        : "+l"(acc[m][j]) : "l"(a2), "l"(b2[j]));
            }
        }
        __syncthreads();
    }
#pragma unroll
    for (int m = 0; m < 8; m++) {
        int gr = bm + ty * 8 + m;
        if (gr < NN) {
#pragma unroll
            for (int j = 0; j < 4; j++) {
                float2 f = upk(acc[m][j]);
                *(__half2*)&C[(size_t)gr * DOUT + tx * 2 + 32 * j] = __float22half2_rn(f);
            }
        }
    }
}

__device__ __forceinline__ void dev_gather(int t, int bx, float* __restrict__ out) {
    int node = bx * 8 + (threadIdx.x >> 5);
    int lane = threadIdx.x & 31;
    const int* off = g_off + t * (NN + 1);
    const int2* csr = g_csr + (size_t)t * EE;
    const __half* y = g_y + (size_t)t * NN * DOUT;
    int beg = off[node], end = off[node + 1];
    float4 acc = make_float4(0.f, 0.f, 0.f, 0.f);
    int e = beg;
    for (; e + 4 <= end; e += 4) {
        int2 c0 = csr[e + 0], c1 = csr[e + 1], c2 = csr[e + 2], c3 = csr[e + 3];
        uint2 r0 = *(const uint2*)&y[(size_t)c0.x * DOUT + lane * 4];
        uint2 r1 = *(const uint2*)&y[(size_t)c1.x * DOUT + lane * 4];
        uint2 r2 = *(const uint2*)&y[(size_t)c2.x * DOUT + lane * 4];
        uint2 r3 = *(const uint2*)&y[(size_t)c3.x * DOUT + lane * 4];
        float w0 = __int_as_float(c0.y), w1 = __int_as_float(c1.y);
        float w2 = __int_as_float(c2.y), w3 = __int_as_float(c3.y);
        float2 a0 = __half22float2(*(__half2*)&r0.x), b0 = __half22float2(*(__half2*)&r0.y);
        float2 a1 = __half22float2(*(__half2*)&r1.x), b1 = __half22float2(*(__half2*)&r1.y);
        float2 a2 = __half22float2(*(__half2*)&r2.x), b2 = __half22float2(*(__half2*)&r2.y);
        float2 a3 = __half22float2(*(__half2*)&r3.x), b3 = __half22float2(*(__half2*)&r3.y);
        acc.x += w0 * a0.x + w1 * a1.x + w2 * a2.x + w3 * a3.x;
        acc.y += w0 * a0.y + w1 * a1.y + w2 * a2.y + w3 * a3.y;
        acc.z += w0 * b0.x + w1 * b1.x + w2 * b2.x + w3 * b3.x;
        acc.w += w0 * b0.y + w1 * b1.y + w2 * b2.y + w3 * b3.y;
    }
    for (; e < end; e++) {
        int2 c0 = csr[e];
        float w0 = __int_as_float(c0.y);
        uint2 r0 = *(const uint2*)&y[(size_t)c0.x * DOUT + lane * 4];
        float2 a0 = __half22float2(*(__half2*)&r0.x), b0 = __half22float2(*(__half2*)&r0.y);
        acc.x += w0 * a0.x; acc.y += w0 * a0.y; acc.z += w0 * b0.x; acc.w += w0 * b0.y;
    }
    acc.x = (acc.x >= 0.f) ? acc.x : SLOPE * acc.x;
    acc.y = (acc.y >= 0.f) ? acc.y : SLOPE * acc.y;
    acc.z = (acc.z >= 0.f) ? acc.z : SLOPE * acc.z;
    acc.w = (acc.w >= 0.f) ? acc.w : SLOPE * acc.w;
    *(float4*)&out[((size_t)t * NN + node) * DOUT + lane * 4] = acc;
}

// ==== pipe: [gruA(t_sg+1)] | sgemm(t_sg) | [fill(t_fill)] | [gather(t_ga)] ====
__global__ __launch_bounds__(256, 2)
void pipe_kernel(int t_sg, int t_ga, int t_fill, int ngru,
                 const float* __restrict__ embs,
                 const int* __restrict__ ei, const float* __restrict__ w,
                 const float* __restrict__ bz, const float* __restrict__ br,
                 float* __restrict__ out) {
    __shared__ __align__(16) char sm[BK * (BM + 1) * 4 + BK * BN * 4];
    int b = blockIdx.x;
    if (b < ngru) { dev_gruA(t_sg + 1, b, bz, br, sm); return; }
    b -= ngru;
    if (b < SGB) { dev_sgemm(t_sg, b, embs, sm); return; }
    b -= SGB;
    if (t_fill >= 0) {
        if (b < 2500) { dev_fill(t_fill, b, ei, w); return; }
        b -= 2500;
    }
    dev_gather(t_ga, b, out);
}

__global__ void gruA0_kernel(const float* __restrict__ bz, const float* __restrict__ br) {
    __shared__ __align__(16) char sm[KT * 128 * 4 + 2 * KT * 16 * 4];
    dev_gruA(0, blockIdx.x, bz, br, sm);
}

__global__ void gather_only_kernel(int t, float* __restrict__ out) {
    dev_gather(t, blockIdx.x, out);
}

// ---------------- launcher ----------------
extern "C" void kernel_launch(void* const* d_in, const int* in_sizes, int n_in,
                              void* d_out, int out_size) {
    const float* node_embs  = (const float*)d_in[0];
    const int*   edge_index = (const int*)d_in[1];
    const float* edge_w     = (const float*)d_in[2];
    const float* mask       = (const float*)d_in[3];
    const float* p          = (const float*)d_in[4];
    const float* Wz         = (const float*)d_in[5];
    const float* Uz         = (const float*)d_in[6];
    const float* bz         = (const float*)d_in[7];
    const float* Wr         = (const float*)d_in[8];
    const float* Ur         = (const float*)d_in[9];
    const float* br         = (const float*)d_in[10];
    const float* Wh         = (const float*)d_in[11];
    const float* Uh         = (const float*)d_in[12];
    const float* bh         = (const float*)d_in[13];
    const float* W0         = (const float*)d_in[14];
    float* out = (float*)d_out;

    front_kernel<<<FB_TOTAL, 256>>>(node_embs, p, mask, edge_index,
                                    Wz, Uz, Wr, Ur, Wh, Uh, W0);
    mid1_kernel<<<36, 1024>>>();
    mid2_kernel<<<4, 1024>>>(node_embs);
    wxfill_kernel<<<64 + 2500, 256>>>(edge_index, edge_w);

    gruA0_kernel<<<16, 256>>>(bz, br);
    gruB_kernel<<<16, 256>>>(0, bh);
    // P1: sgemm(0) + gruA(1) + fill(1)
    pipe_kernel<<<16 + SGB + 2500, 256>>>(0, -1, 1, 16, node_embs,
                                          edge_index, edge_w, bz, br, out);
    gruB_kernel<<<16, 256>>>(1, bh);
    // P2: sgemm(1) + gruA(2) + fill(2) + gather(0)
    pipe_kernel<<<16 + SGB + 2500 + 2500, 256>>>(1, 0, 2, 16, node_embs,
                                                 edge_index, edge_w, bz, br, out);
    gruB_kernel<<<16, 256>>>(2, bh);
    // P3: sgemm(2) + gruA(3) + fill(3) + gather(1)
    pipe_kernel<<<16 + SGB + 2500 + 2500, 256>>>(2, 1, 3, 16, node_embs,
                                                 edge_index, edge_w, bz, br, out);
    gruB_kernel<<<16, 256>>>(3, bh);
    // P4: sgemm(3) + gather(2)
    pipe_kernel<<<SGB + 2500, 256>>>(3, 2, -1, 0, node_embs,
                                     edge_index, edge_w, bz, br, out);
    gather_only_kernel<<<2500, 256>>>(3, out);
}

// round 6
// speedup vs baseline: 1.7462x; 1.1128x over previous
#include <cuda_runtime.h>
#include <cuda_fp16.h>

#define TT   4
#define NN   20000
#define EE   640000
#define DIN  256
#define DOUT 128
#define MAT  (DIN * DOUT)      // 32768
#define MSQ  (DIN * DIN)       // 65536
#define SLOPE 0.22916666666666666f

typedef unsigned long long ull;

// ---------------- scratch (__device__ globals; no allocation) ----------------
__device__ float g_scores[TT * NN];
__device__ float g_xt[TT * MAT];             // per-t [256][128]
__device__ float g_Wn[(TT + 1) * MAT];       // W0 + evolved weights
__device__ float g_WT[6 * MSQ];              // transposed Wz,Uz,Wr,Ur,Wh,Uh
__device__ float g_WX[3 * TT * MAT];         // Wz@xt, Wr@xt, Wh@xt per t
__device__ float g_z[MAT];
__device__ float g_rW[MAT];
__device__ __half g_y[(size_t)TT * NN * DOUT];   // fp16 y (halves gather traffic)
__device__ int   g_deg[TT * NN];
__device__ int   g_off[TT * (NN + 1)];
__device__ int   g_cur[TT * NN];
__device__ int2  g_csr[(size_t)TT * EE];
__device__ int   g_hist[TT * 4096];

// ---------------- helpers ----------------
__device__ __forceinline__ unsigned ord_of(float f) {
    unsigned b = __float_as_uint(f);
    return b ^ ((b & 0x80000000u) ? 0xFFFFFFFFu : 0x80000000u);
}
__device__ __forceinline__ float sigmoidf_(float x) {
    return 1.0f / (1.0f + expf(-x));
}
__device__ __forceinline__ float2 upk(ull v) {
    float2 r;
    asm("mov.b64 {%0, %1}, %2;" : "=f"(r.x), "=f"(r.y) : "l"(v));
    return r;
}
__device__ __forceinline__ ull dup2(float a) {
    ull r;
    asm("mov.b64 %0, {%1, %1};" : "=l"(r) : "f"(a));
    return r;
}

// ================= L1: front = scores | deg | prep-transpose | hist-zero =====
#define FB_SCORES 10000
#define FB_DEG    10000
#define FB_PREP   1664
#define FB_HZERO  64
#define FB_TOTAL  (FB_SCORES + FB_DEG + FB_PREP + FB_HZERO)

__global__ void front_kernel(const float* __restrict__ embs,
                             const float* __restrict__ p,
                             const float* __restrict__ mask,
                             const int* __restrict__ ei,
                             const float* __restrict__ Wz, const float* __restrict__ Uz,
                             const float* __restrict__ Wr, const float* __restrict__ Ur,
                             const float* __restrict__ Wh, const float* __restrict__ Uh,
                             const float* __restrict__ W0) {
    int b = blockIdx.x;
    int tid = threadIdx.x;
    if (b < FB_SCORES) {
        __shared__ float sp[DIN];
        sp[tid] = p[tid];
        __syncthreads();
        int t = b / 2500;
        int warp = tid >> 5, lane = tid & 31;
        int n = (b % 2500) * 8 + warp;
        const float* xr = embs + ((size_t)t * NN + n) * DIN;
        float4 x0 = *(const float4*)&xr[lane * 4];
        float4 x1 = *(const float4*)&xr[128 + lane * 4];
        float4 p0 = *(const float4*)&sp[lane * 4];
        float4 p1 = *(const float4*)&sp[128 + lane * 4];
        float s = x0.x * p0.x + x0.y * p0.y + x0.z * p0.z + x0.w * p0.w
                + x1.x * p1.x + x1.y * p1.y + x1.z * p1.z + x1.w * p1.w;
        float q = p0.x * p0.x + p0.y * p0.y + p0.z * p0.z + p0.w * p0.w
                + p1.x * p1.x + p1.y * p1.y + p1.z * p1.z + p1.w * p1.w;
#pragma unroll
        for (int o = 16; o > 0; o >>= 1) {
            s += __shfl_down_sync(0xFFFFFFFFu, s, o);
            q += __shfl_down_sync(0xFFFFFFFFu, q, o);
        }
        if (lane == 0) g_scores[t * NN + n] = s * rsqrtf(q) + mask[t * NN + n];
    } else if (b < FB_SCORES + FB_DEG) {
        int idx = b - FB_SCORES;
        int t = idx / 2500;
        int e = (idx % 2500) * 256 + tid;
        const int* dst = ei + (size_t)t * 2 * EE;
        atomicAdd(&g_deg[t * NN + dst[e]], 1);
    } else if (b < FB_SCORES + FB_DEG + FB_PREP) {
        int idx = (b - FB_SCORES - FB_DEG) * 256 + tid;
        const float* srcs[6] = {Wz, Uz, Wr, Ur, Wh, Uh};
        if (idx < 6 * MSQ) {
            int m = idx >> 16;
            int e = idx & 0xFFFF;
            int k = e >> 8, i = e & 255;
            g_WT[idx] = srcs[m][i * DIN + k];
        } else {
            int e = idx - 6 * MSQ;
            g_Wn[e] = W0[e];
        }
    } else {
        int i = (b - FB_SCORES - FB_DEG - FB_PREP) * 256 + tid;
        if (i < TT * 4096) g_hist[i] = 0;
    }
}

// ================= L2: mid1 = hist(32 blocks) | scan(4 blocks) ================
__device__ void do_scan(int t) {
    __shared__ int part[1024];
    int tid = threadIdx.x;
    int* deg = g_deg + t * NN;
    int* off = g_off + t * (NN + 1);
    int* cur = g_cur + t * NN;
    int base = tid * 20;
    int loc[20];
    int sum = 0;
#pragma unroll
    for (int i = 0; i < 20; i++) {
        int n = base + i;
        int d = (n < NN) ? deg[n] : 0;
        if (n < NN) deg[n] = 0;     // re-zero for graph replay
        loc[i] = sum;
        sum += d;
    }
    part[tid] = sum;
    __syncthreads();
    for (int o = 1; o < 1024; o <<= 1) {
        int v = (tid >= o) ? part[tid - o] : 0;
        __syncthreads();
        part[tid] += v;
        __syncthreads();
    }
    int myoff = tid ? part[tid - 1] : 0;
#pragma unroll
    for (int i = 0; i < 20; i++) {
        int n = base + i;
        if (n <= NN) {
            int o = myoff + loc[i];
            off[n] = o;
            if (n < NN) cur[n] = o;
        }
    }
}

__global__ void mid1_kernel() {
    int b = blockIdx.x;
    int tid = threadIdx.x;   // 1024
    if (b < 32) {
        __shared__ int h[4096];
        int t = b >> 3, chunk = b & 7;
#pragma unroll
        for (int j = 0; j < 4; j++) h[tid + j * 1024] = 0;
        __syncthreads();
        const float* scores = g_scores + t * NN;
        int base = chunk * 2500;
        for (int n = base + tid; n < base + 2500; n += 1024)
            atomicAdd(&h[ord_of(scores[n]) >> 20], 1);
        __syncthreads();
#pragma unroll
        for (int j = 0; j < 4; j++) {
            int bin = tid + j * 1024;
            int v = h[bin];
            if (v) atomicAdd(&g_hist[t * 4096 + bin], v);
        }
    } else {
        do_scan(b - 32);
    }
}

// ================= L3: mid2 = per-t select + xt build ========================
__global__ void mid2_kernel(const float* __restrict__ embs) {
    int t = blockIdx.x;
    int tid = threadIdx.x;   // 1024
    __shared__ int part[1024];
    __shared__ int sB, sAbove;
    __shared__ unsigned cnt_gt, cnt_cand;
    __shared__ unsigned sel_ord[DOUT];
    __shared__ int sel_idx[DOUT];
    __shared__ unsigned cand_ord[512];
    __shared__ int cand_idx[512];
    __shared__ int sh_idx[DOUT];
    __shared__ float sh_tanh[DOUT];

    const float* scores = g_scores + t * NN;
    const int* hist = g_hist + t * 4096;

    int cnt[4];
    int s = 0;
#pragma unroll
    for (int j = 0; j < 4; j++) {
        int bin = 4095 - (tid * 4 + j);
        cnt[j] = hist[bin];
        s += cnt[j];
    }
    part[tid] = s;
    if (tid == 0) { cnt_gt = 0; cnt_cand = 0; }
    __syncthreads();
    for (int o = 1; o < 1024; o <<= 1) {
        int v = (tid >= o) ? part[tid - o] : 0;
        __syncthreads();
        part[tid] += v;
        __syncthreads();
    }
    int c = tid ? part[tid - 1] : 0;
#pragma unroll
    for (int j = 0; j < 4; j++) {
        int bin = 4095 - (tid * 4 + j);
        if (c < DOUT && c + cnt[j] >= DOUT) { sB = bin; sAbove = c; }
        c += cnt[j];
    }
    __syncthreads();
    int B = sB, above = sAbove, kneed = DOUT - above;

    for (int n = tid; n < NN; n += 1024) {
        unsigned ord = ord_of(scores[n]);
        int bucket = ord >> 20;
        if (bucket > B) {
            unsigned pos = atomicAdd(&cnt_gt, 1u);
            sel_ord[pos] = ord; sel_idx[pos] = n;
        } else if (bucket == B) {
            unsigned pos = atomicAdd(&cnt_cand, 1u);
            if (pos < 512) { cand_ord[pos] = ord; cand_idx[pos] = n; }
        }
    }
    __syncthreads();
    int nc = (int)cnt_cand; if (nc > 512) nc = 512;
    for (int ci = tid; ci < nc; ci += 1024) {
        unsigned mo = cand_ord[ci];
        int mi = cand_idx[ci];
        int r = 0;
        for (int j = 0; j < nc; j++) {
            unsigned o = cand_ord[j];
            r += (o > mo) || (o == mo && cand_idx[j] < mi);
        }
        if (r < kneed) { sel_ord[above + r] = mo; sel_idx[above + r] = mi; }
    }
    __syncthreads();
    if (tid < DOUT) {
        unsigned mo = sel_ord[tid];
        int mi = sel_idx[tid];
        int r = 0;
#pragma unroll 4
        for (int i = 0; i < DOUT; i++) {
            unsigned o = sel_ord[i];
            r += (o > mo) || (o == mo && sel_idx[i] < mi);
        }
        sh_idx[r] = mi;
        sh_tanh[r] = tanhf(scores[mi]);
    }
    __syncthreads();
    float* xt = g_xt + t * MAT;
    for (int e = tid; e < MAT; e += 1024) {
        int j = e >> 8;
        int d = e & 255;
        xt[d * DOUT + j] = embs[((size_t)t * NN + sh_idx[j]) * DIN + d] * sh_tanh[j];
    }
}

// ================= small GEMM: 16x128 tile, K=256, up to 3 A-mats sharing B ===
#define KT 32
template <int NMAT>
__device__ __forceinline__ void gemm16(const float* __restrict__ AT0,
                                       const float* __restrict__ AT1,
                                       const float* __restrict__ AT2,
                                       const float* __restrict__ Bmat,
                                       int i0, ull a0[4], ull a1[4], ull a2[4],
                                       char* sm) {
    float (*Bs)[128] = (float(*)[128])sm;
    float (*As)[16]  = (float(*)[16])(sm + KT * 128 * 4);
    int tid = threadIdx.x;           // 256
    int ti = tid & 15, tj = tid >> 4;
    int brow = tid >> 5, bcol = (tid & 31) * 4;
    int akk = tid >> 4, aii = tid & 15;

    float4 pb[4];
    float pa0[2], pa1[2], pa2[2];
#pragma unroll
    for (int l = 0; l < 4; l++)
        pb[l] = *(const float4*)&Bmat[(brow + 8 * l) * 128 + bcol];
#pragma unroll
    for (int l = 0; l < 2; l++) {
        int kk = akk + 16 * l;
        pa0[l] = AT0[kk * DIN + i0 + aii];
        if (NMAT > 1) pa1[l] = AT1[kk * DIN + i0 + aii];
        if (NMAT > 2) pa2[l] = AT2[kk * DIN + i0 + aii];
    }
    for (int k0 = 0; k0 < DIN; k0 += KT) {
#pragma unroll
        for (int l = 0; l < 4; l++)
            *(float4*)&Bs[brow + 8 * l][bcol] = pb[l];
#pragma unroll
        for (int l = 0; l < 2; l++) {
            int kk = akk + 16 * l;
            As[0 * KT + kk][aii] = pa0[l];
            if (NMAT > 1) As[1 * KT + kk][aii] = pa1[l];
            if (NMAT > 2) As[2 * KT + kk][aii] = pa2[l];
        }
        __syncthreads();
        int kn = k0 + KT;
        if (kn < DIN) {
#pragma unroll
            for (int l = 0; l < 4; l++)
                pb[l] = *(const float4*)&Bmat[(kn + brow + 8 * l) * 128 + bcol];
#pragma unroll
            for (int l = 0; l < 2; l++) {
                int kk = kn + akk + 16 * l;
                pa0[l] = AT0[kk * DIN + i0 + aii];
                if (NMAT > 1) pa1[l] = AT1[kk * DIN + i0 + aii];
                if (NMAT > 2) pa2[l] = AT2[kk * DIN + i0 + aii];
            }
        }
#pragma unroll
        for (int kk = 0; kk < KT; kk++) {
            ull b[4];
            b[0] = *(const ull*)&Bs[kk][tj * 8 + 0];
            b[1] = *(const ull*)&Bs[kk][tj * 8 + 2];
            b[2] = *(const ull*)&Bs[kk][tj * 8 + 4];
            b[3] = *(const ull*)&Bs[kk][tj * 8 + 6];
            {
                ull av = dup2(As[0 * KT + kk][ti]);
#pragma unroll
                for (int j = 0; j < 4; j++)
                    asm("fma.rn.f32x2 %0, %1, %2, %0;" : "+l"(a0[j]) : "l"(av), "l"(b[j]));
            }
            if (NMAT > 1) {
                ull av = dup2(As[1 * KT + kk][ti]);
#pragma unroll
                for (int j = 0; j < 4; j++)
                    asm("fma.rn.f32x2 %0, %1, %2, %0;" : "+l"(a1[j]) : "l"(av), "l"(b[j]));
            }
            if (NMAT > 2) {
                ull av = dup2(As[2 * KT + kk][ti]);
#pragma unroll
                for (int j = 0; j < 4; j++)
                    asm("fma.rn.f32x2 %0, %1, %2, %0;" : "+l"(a2[j]) : "l"(av), "l"(b[j]));
            }
        }
        __syncthreads();
    }
}

// ---- gruA: z = sig(WXz + Uz@W + bz), r = sig(WXr + Ur@W + br), rW = r*W ------
__device__ __forceinline__ void dev_gruA(int t, int bx,
                                         const float* __restrict__ bz,
                                         const float* __restrict__ br,
                                         char* sm) {
    int i0 = bx * 16;
    ull a0[4] = {0, 0, 0, 0}, a1[4] = {0, 0, 0, 0};
    gemm16<2>(g_WT + 1 * MSQ, g_WT + 3 * MSQ, (const float*)0,
              g_Wn + t * MAT, i0, a0, a1, a0, sm);
    int ti = threadIdx.x & 15, tj = threadIdx.x >> 4;
    int row = i0 + ti, col = tj * 8;
    const float* WXz = g_WX + (0 * TT + t) * MAT;
    const float* WXr = g_WX + (1 * TT + t) * MAT;
    const float* Wt  = g_Wn + t * MAT;
#pragma unroll
    for (int j = 0; j < 4; j++) {
        int o = row * DOUT + col + 2 * j;
        float2 az = upk(a0[j]), ar = upk(a1[j]);
        float2 xz = *(const float2*)&WXz[o];
        float2 xr = *(const float2*)&WXr[o];
        float2 vz = *(const float2*)&bz[o];
        float2 vr = *(const float2*)&br[o];
        float2 wv = *(const float2*)&Wt[o];
        float2 z2, rw2;
        z2.x = sigmoidf_(az.x + xz.x + vz.x);
        z2.y = sigmoidf_(az.y + xz.y + vz.y);
        rw2.x = sigmoidf_(ar.x + xr.x + vr.x) * wv.x;
        rw2.y = sigmoidf_(ar.y + xr.y + vr.y) * wv.y;
        *(float2*)&g_z[o] = z2;
        *(float2*)&g_rW[o] = rw2;
    }
}

// ---- gruB: h = tanh(WXh + Uh@rW + bh); Wn_{t+1} = W + z*(h - W) --------------
__global__ void gruB_kernel(int t, const float* __restrict__ bh) {
    __shared__ __align__(16) char sm[KT * 128 * 4 + KT * 16 * 4];
    int i0 = blockIdx.x * 16;
    ull a0[4] = {0, 0, 0, 0};
    gemm16<1>(g_WT + 5 * MSQ, (const float*)0, (const float*)0,
              g_rW, i0, a0, a0, a0, sm);
    int ti = threadIdx.x & 15, tj = threadIdx.x >> 4;
    int row = i0 + ti, col = tj * 8;
    const float* WXh = g_WX + (2 * TT + t) * MAT;
    const float* Wt  = g_Wn + t * MAT;
    float* Wnx = g_Wn + (t + 1) * MAT;
#pragma unroll
    for (int j = 0; j < 4; j++) {
        int o = row * DOUT + col + 2 * j;
        float2 ah = upk(a0[j]);
        float2 xh = *(const float2*)&WXh[o];
        float2 vh = *(const float2*)&bh[o];
        float2 wv = *(const float2*)&Wt[o];
        float2 z2 = *(const float2*)&g_z[o];
        float hx = tanhf(ah.x + xh.x + vh.x);
        float hy = tanhf(ah.y + xh.y + vh.y);
        float2 wn;
        wn.x = wv.x + z2.x * (hx - wv.x);
        wn.y = wv.y + z2.y * (hy - wv.y);
        *(float2*)&Wnx[o] = wn;
    }
}

// ---- CSR fill body (2500 blocks per t) ---------------------------------------
__device__ __forceinline__ void dev_fill(int t, int bx,
                                         const int* __restrict__ ei,
                                         const float* __restrict__ w) {
    int e = bx * 256 + threadIdx.x;
    const int* dst = ei + (size_t)t * 2 * EE;
    const int* src = dst + EE;
    int d = dst[e];
    int pos = atomicAdd(&g_cur[t * NN + d], 1);
    g_csr[(size_t)t * EE + pos] = make_int2(src[e], __float_as_int(w[(size_t)t * EE + e]));
}

// ================= wxfill: WX GEMMs (64 blocks) | fill(0) (2500) ==============
__global__ void wxfill_kernel(const int* __restrict__ ei, const float* __restrict__ w) {
    int b = blockIdx.x;
    if (b < 64) {
        __shared__ __align__(16) char sm[KT * 128 * 4 + 3 * KT * 16 * 4];
        int t = b >> 4, i0 = (b & 15) * 16;
        ull a0[4] = {0, 0, 0, 0}, a1[4] = {0, 0, 0, 0}, a2[4] = {0, 0, 0, 0};
        gemm16<3>(g_WT + 0 * MSQ, g_WT + 2 * MSQ, g_WT + 4 * MSQ,
                  g_xt + t * MAT, i0, a0, a1, a2, sm);
        int ti = threadIdx.x & 15, tj = threadIdx.x >> 4;
        int base = (i0 + ti) * DOUT + tj * 8;
#pragma unroll
        for (int j = 0; j < 4; j++) {
            *(ull*)&g_WX[(0 * TT + t) * MAT + base + 2 * j] = a0[j];
            *(ull*)&g_WX[(1 * TT + t) * MAT + base + 2 * j] = a1[j];
            *(ull*)&g_WX[(2 * TT + t) * MAT + base + 2 * j] = a2[j];
        }
    } else {
        dev_fill(0, b - 64, ei, w);
    }
}

// ================= sgemm (BM=64: 313 blocks/t fills the chip) =================
#define BM 64
#define BN 128
#define BK 32
#define SGB ((NN + BM - 1) / BM)   // 313

__device__ __forceinline__ void dev_sgemm(int t, int bx, const float* __restrict__ embs,
                                          char* sm) {
    float (*As)[BM + 1] = (float(*)[BM + 1])sm;                      // [32][65]
    float (*Bs)[BN]     = (float(*)[BN])(sm + BK * (BM + 1) * 4);    // [32][128]
    const float* A = embs + (size_t)t * NN * DIN;
    const float* B = g_Wn + (t + 1) * MAT;
    __half* C = g_y + (size_t)t * NN * DOUT;

    int tid = threadIdx.x;           // 256
    int bm = bx * BM;
    int tx = tid & 15;               // col pairs tx*2 + 32j
    int ty = tid >> 4;               // rows ty*4 .. ty*4+3
    int ar = tid >> 2;               // A-load row (0..63)
    int aq = tid & 3;                // A-load quad group

    ull acc[4][4];
#pragma unroll
    for (int m = 0; m < 4; m++)
#pragma unroll
        for (int j = 0; j < 4; j++) acc[m][j] = 0ull;

    float4 pa[2], pb[4];
#pragma unroll
    for (int l = 0; l < 2; l++) {
        int gr = bm + ar;
        int kq = aq * 4 + l * 16;
        pa[l] = (gr < NN) ? *(const float4*)&A[(size_t)gr * DIN + kq]
                          : make_float4(0.f, 0.f, 0.f, 0.f);
    }
#pragma unroll
    for (int l = 0; l < 4; l++) {
        int q = l * 256 + tid;
        pb[l] = *(const float4*)&B[(q >> 5) * BN + (q & 31) * 4];
    }

    for (int k0 = 0; k0 < DIN; k0 += BK) {
#pragma unroll
        for (int l = 0; l < 2; l++) {
            int kq = aq * 4 + l * 16;
            As[kq + 0][ar] = pa[l].x;
            As[kq + 1][ar] = pa[l].y;
            As[kq + 2][ar] = pa[l].z;
            As[kq + 3][ar] = pa[l].w;
        }
#pragma unroll
        for (int l = 0; l < 4; l++) {
            int q = l * 256 + tid;
            *(float4*)&Bs[q >> 5][(q & 31) * 4] = pb[l];
        }
        __syncthreads();
        int kn = k0 + BK;
        if (kn < DIN) {
#pragma unroll
            for (int l = 0; l < 2; l++) {
                int gr = bm + ar;
                int kq = aq * 4 + l * 16;
                pa[l] = (gr < NN) ? *(const float4*)&A[(size_t)gr * DIN + kn + kq]
                                  : make_float4(0.f, 0.f, 0.f, 0.f);
            }
#pragma unroll
            for (int l = 0; l < 4; l++) {
                int q = l * 256 + tid;
                pb[l] = *(const float4*)&B[(kn + (q >> 5)) * BN + (q & 31) * 4];
            }
        }
#pragma unroll
        for (int kk = 0; kk < BK; kk++) {
            ull b2[4];
#pragma unroll
            for (int j = 0; j < 4; j++)
                b2[j] = *(const ull*)&Bs[kk][tx * 2 + 32 * j];
#pragma unroll
            for (int m = 0; m < 4; m++) {
                ull a2 = dup2(As[kk][ty * 4 + m]);
#pragma unroll
                for (int j = 0; j < 4; j++)
                    asm("fma.rn.f32x2 %0, %1, %2, %0;"
                        : "+l"(acc[m][j]) : "l"(a2), "l"(b2[j]));
            }
        }
        __syncthreads();
    }
#pragma unroll
    for (int m = 0; m < 4; m++) {
        int gr = bm + ty * 4 + m;
        if (gr < NN) {
#pragma unroll
            for (int j = 0; j < 4; j++) {
                float2 f = upk(acc[m][j]);
                *(__half2*)&C[(size_t)gr * DOUT + tx * 2 + 32 * j] = __float22half2_rn(f);
            }
        }
    }
}

__device__ __forceinline__ void dev_gather(int t, int bx, float* __restrict__ out) {
    int node = bx * 8 + (threadIdx.x >> 5);
    int lane = threadIdx.x & 31;
    const int* off = g_off + t * (NN + 1);
    const int2* csr = g_csr + (size_t)t * EE;
    const __half* y = g_y + (size_t)t * NN * DOUT;
    int beg = off[node], end = off[node + 1];
    float4 acc = make_float4(0.f, 0.f, 0.f, 0.f);
    int e = beg;
    for (; e + 4 <= end; e += 4) {
        int2 c0 = csr[e + 0], c1 = csr[e + 1], c2 = csr[e + 2], c3 = csr[e + 3];
        uint2 r0 = *(const uint2*)&y[(size_t)c0.x * DOUT + lane * 4];
        uint2 r1 = *(const uint2*)&y[(size_t)c1.x * DOUT + lane * 4];
        uint2 r2 = *(const uint2*)&y[(size_t)c2.x * DOUT + lane * 4];
        uint2 r3 = *(const uint2*)&y[(size_t)c3.x * DOUT + lane * 4];
        float w0 = __int_as_float(c0.y), w1 = __int_as_float(c1.y);
        float w2 = __int_as_float(c2.y), w3 = __int_as_float(c3.y);
        float2 a0 = __half22float2(*(__half2*)&r0.x), b0 = __half22float2(*(__half2*)&r0.y);
        float2 a1 = __half22float2(*(__half2*)&r1.x), b1 = __half22float2(*(__half2*)&r1.y);
        float2 a2 = __half22float2(*(__half2*)&r2.x), b2 = __half22float2(*(__half2*)&r2.y);
        float2 a3 = __half22float2(*(__half2*)&r3.x), b3 = __half22float2(*(__half2*)&r3.y);
        acc.x += w0 * a0.x + w1 * a1.x + w2 * a2.x + w3 * a3.x;
        acc.y += w0 * a0.y + w1 * a1.y + w2 * a2.y + w3 * a3.y;
        acc.z += w0 * b0.x + w1 * b1.x + w2 * b2.x + w3 * b3.x;
        acc.w += w0 * b0.y + w1 * b1.y + w2 * b2.y + w3 * b3.y;
    }
    for (; e < end; e++) {
        int2 c0 = csr[e];
        float w0 = __int_as_float(c0.y);
        uint2 r0 = *(const uint2*)&y[(size_t)c0.x * DOUT + lane * 4];
        float2 a0 = __half22float2(*(__half2*)&r0.x), b0 = __half22float2(*(__half2*)&r0.y);
        acc.x += w0 * a0.x; acc.y += w0 * a0.y; acc.z += w0 * b0.x; acc.w += w0 * b0.y;
    }
    acc.x = (acc.x >= 0.f) ? acc.x : SLOPE * acc.x;
    acc.y = (acc.y >= 0.f) ? acc.y : SLOPE * acc.y;
    acc.z = (acc.z >= 0.f) ? acc.z : SLOPE * acc.z;
    acc.w = (acc.w >= 0.f) ? acc.w : SLOPE * acc.w;
    *(float4*)&out[((size_t)t * NN + node) * DOUT + lane * 4] = acc;
}

// ==== pipe: [gruA(t_sg+1)] | sgemm(t_sg) | [fill(t_fill)] | [gather(t_ga)] ====
__global__ __launch_bounds__(256, 3)
void pipe_kernel(int t_sg, int t_ga, int t_fill, int ngru,
                 const float* __restrict__ embs,
                 const int* __restrict__ ei, const float* __restrict__ w,
                 const float* __restrict__ bz, const float* __restrict__ br,
                 float* __restrict__ out) {
    __shared__ __align__(16) char sm[BK * (BM + 1) * 4 + BK * BN * 4];
    int b = blockIdx.x;
    if (b < ngru) { dev_gruA(t_sg + 1, b, bz, br, sm); return; }
    b -= ngru;
    if (b < SGB) { dev_sgemm(t_sg, b, embs, sm); return; }
    b -= SGB;
    if (t_fill >= 0) {
        if (b < 2500) { dev_fill(t_fill, b, ei, w); return; }
        b -= 2500;
    }
    dev_gather(t_ga, b, out);
}

__global__ void gruA0_kernel(const float* __restrict__ bz, const float* __restrict__ br) {
    __shared__ __align__(16) char sm[KT * 128 * 4 + 2 * KT * 16 * 4];
    dev_gruA(0, blockIdx.x, bz, br, sm);
}

__global__ void gather_only_kernel(int t, float* __restrict__ out) {
    dev_gather(t, blockIdx.x, out);
}

// ---------------- launcher ----------------
extern "C" void kernel_launch(void* const* d_in, const int* in_sizes, int n_in,
                              void* d_out, int out_size) {
    const float* node_embs  = (const float*)d_in[0];
    const int*   edge_index = (const int*)d_in[1];
    const float* edge_w     = (const float*)d_in[2];
    const float* mask       = (const float*)d_in[3];
    const float* p          = (const float*)d_in[4];
    const float* Wz         = (const float*)d_in[5];
    const float* Uz         = (const float*)d_in[6];
    const float* bz         = (const float*)d_in[7];
    const float* Wr         = (const float*)d_in[8];
    const float* Ur         = (const float*)d_in[9];
    const float* br         = (const float*)d_in[10];
    const float* Wh         = (const float*)d_in[11];
    const float* Uh         = (const float*)d_in[12];
    const float* bh         = (const float*)d_in[13];
    const float* W0         = (const float*)d_in[14];
    float* out = (float*)d_out;

    front_kernel<<<FB_TOTAL, 256>>>(node_embs, p, mask, edge_index,
                                    Wz, Uz, Wr, Ur, Wh, Uh, W0);
    mid1_kernel<<<36, 1024>>>();
    mid2_kernel<<<4, 1024>>>(node_embs);
    wxfill_kernel<<<64 + 2500, 256>>>(edge_index, edge_w);

    gruA0_kernel<<<16, 256>>>(bz, br);
    gruB_kernel<<<16, 256>>>(0, bh);
    // P1: sgemm(0) + gruA(1) + fill(1)
    pipe_kernel<<<16 + SGB + 2500, 256>>>(0, -1, 1, 16, node_embs,
                                          edge_index, edge_w, bz, br, out);
    gruB_kernel<<<16, 256>>>(1, bh);
    // P2: sgemm(1) + gruA(2) + fill(2) + gather(0)
    pipe_kernel<<<16 + SGB + 2500 + 2500, 256>>>(1, 0, 2, 16, node_embs,
                                                 edge_index, edge_w, bz, br, out);
    gruB_kernel<<<16, 256>>>(2, bh);
    // P3: sgemm(2) + gruA(3) + fill(3) + gather(1)
    pipe_kernel<<<16 + SGB + 2500 + 2500, 256>>>(2, 1, 3, 16, node_embs,
                                                 edge_index, edge_w, bz, br, out);
    gruB_kernel<<<16, 256>>>(3, bh);
    // P4: sgemm(3) + gather(2)
    pipe_kernel<<<SGB + 2500, 256>>>(3, 2, -1, 0, node_embs,
                                     edge_index, edge_w, bz, br, out);
    gather_only_kernel<<<2500, 256>>>(3, out);
}

// round 7
// speedup vs baseline: 2.2499x; 1.2885x over previous
#include <cuda_runtime.h>
#include <cuda_fp16.h>

#define TT   4
#define NN   20000
#define EE   640000
#define DIN  256
#define DOUT 128
#define MAT  (DIN * DOUT)      // 32768
#define MSQ  (DIN * DIN)       // 65536
#define SLOPE 0.22916666666666666f

typedef unsigned long long ull;

// ---------------- scratch (__device__ globals; no allocation) ----------------
__device__ float  g_scores[TT * NN];
__device__ float  g_xt[TT * MAT];             // per-t [256][128]
__device__ float  g_Wn[(TT + 1) * MAT];       // W0 + evolved weights (fp32)
__device__ __half g_Wh[TT * MAT];             // Wn(t+1) fp16 for the y-GEMM
__device__ __half g_xh[(size_t)TT * NN * DIN];// fp16 copy of node_embs (41 MB)
__device__ float  g_WT[6 * MSQ];              // transposed Wz,Uz,Wr,Ur,Wh,Uh
__device__ float  g_WX[3 * TT * MAT];         // Wz@xt, Wr@xt, Wh@xt per t
__device__ float  g_z[MAT];
__device__ float  g_rW[MAT];
__device__ __half g_y[(size_t)TT * NN * DOUT];
__device__ int    g_deg[TT * NN];
__device__ int    g_off[TT * (NN + 1)];
__device__ int    g_cur[TT * NN];
__device__ int2   g_csr[(size_t)TT * EE];
__device__ int    g_hist[TT * 4096];          // zero-init; re-zeroed in mid2

// ---------------- helpers ----------------
__device__ __forceinline__ unsigned ord_of(float f) {
    unsigned b = __float_as_uint(f);
    return b ^ ((b & 0x80000000u) ? 0xFFFFFFFFu : 0x80000000u);
}
__device__ __forceinline__ float sigmoidf_(float x) {
    return 1.0f / (1.0f + expf(-x));
}
__device__ __forceinline__ float2 upk(ull v) {
    float2 r;
    asm("mov.b64 {%0, %1}, %2;" : "=f"(r.x), "=f"(r.y) : "l"(v));
    return r;
}
__device__ __forceinline__ ull dup2(float a) {
    ull r;
    asm("mov.b64 %0, {%1, %1};" : "=l"(r) : "f"(a));
    return r;
}
__device__ __forceinline__ unsigned smaddr(const void* p) {
    return (unsigned)__cvta_generic_to_shared(p);
}

// ================= L1: front = scores+hist+fp16copy | deg | prep =============
#define FB_SCORES 10000
#define FB_DEG    10000
#define FB_PREP   1664
#define FB_TOTAL  (FB_SCORES + FB_DEG + FB_PREP)

__global__ void front_kernel(const float* __restrict__ embs,
                             const float* __restrict__ p,
                             const float* __restrict__ mask,
                             const int* __restrict__ ei,
                             const float* __restrict__ Wz, const float* __restrict__ Uz,
                             const float* __restrict__ Wr, const float* __restrict__ Ur,
                             const float* __restrict__ Wh, const float* __restrict__ Uh,
                             const float* __restrict__ W0) {
    int b = blockIdx.x;
    int tid = threadIdx.x;
    if (b < FB_SCORES) {
        __shared__ float sp[DIN];
        sp[tid] = p[tid];
        __syncthreads();
        int t = b / 2500;
        int warp = tid >> 5, lane = tid & 31;
        int n = (b % 2500) * 8 + warp;
        const float* xr = embs + ((size_t)t * NN + n) * DIN;
        float4 x0 = *(const float4*)&xr[lane * 4];
        float4 x1 = *(const float4*)&xr[128 + lane * 4];
        // fp16 copy of the row (for the tensor-core y-GEMM)
        __half* xh = g_xh + ((size_t)t * NN + n) * DIN;
        *(__half2*)&xh[lane * 4]           = __floats2half2_rn(x0.x, x0.y);
        *(__half2*)&xh[lane * 4 + 2]       = __floats2half2_rn(x0.z, x0.w);
        *(__half2*)&xh[128 + lane * 4]     = __floats2half2_rn(x1.x, x1.y);
        *(__half2*)&xh[128 + lane * 4 + 2] = __floats2half2_rn(x1.z, x1.w);
        float4 p0 = *(const float4*)&sp[lane * 4];
        float4 p1 = *(const float4*)&sp[128 + lane * 4];
        float s = x0.x * p0.x + x0.y * p0.y + x0.z * p0.z + x0.w * p0.w
                + x1.x * p1.x + x1.y * p1.y + x1.z * p1.z + x1.w * p1.w;
        float q = p0.x * p0.x + p0.y * p0.y + p0.z * p0.z + p0.w * p0.w
                + p1.x * p1.x + p1.y * p1.y + p1.z * p1.z + p1.w * p1.w;
#pragma unroll
        for (int o = 16; o > 0; o >>= 1) {
            s += __shfl_down_sync(0xFFFFFFFFu, s, o);
            q += __shfl_down_sync(0xFFFFFFFFu, q, o);
        }
        if (lane == 0) {
            float sc = s * rsqrtf(q) + mask[t * NN + n];
            g_scores[t * NN + n] = sc;
            atomicAdd(&g_hist[t * 4096 + (ord_of(sc) >> 20)], 1);
        }
    } else if (b < FB_SCORES + FB_DEG) {
        int idx = b - FB_SCORES;
        int t = idx / 2500;
        int e = (idx % 2500) * 256 + tid;
        const int* dst = ei + (size_t)t * 2 * EE;
        atomicAdd(&g_deg[t * NN + dst[e]], 1);
    } else {
        int idx = (b - FB_SCORES - FB_DEG) * 256 + tid;
        const float* srcs[6] = {Wz, Uz, Wr, Ur, Wh, Uh};
        if (idx < 6 * MSQ) {
            int m = idx >> 16;
            int e = idx & 0xFFFF;
            int k = e >> 8, i = e & 255;
            g_WT[idx] = srcs[m][i * DIN + k];
        } else {
            int e = idx - 6 * MSQ;
            g_Wn[e] = W0[e];
        }
    }
}

// ================= L2: mid2s = select+xt (blocks 0-3) | scan (blocks 4-7) =====
__device__ void do_scan(int t) {
    __shared__ int part[1024];
    int tid = threadIdx.x;
    int* deg = g_deg + t * NN;
    int* off = g_off + t * (NN + 1);
    int* cur = g_cur + t * NN;
    int base = tid * 20;
    int loc[20];
    int sum = 0;
#pragma unroll
    for (int i = 0; i < 20; i++) {
        int n = base + i;
        int d = (n < NN) ? deg[n] : 0;
        if (n < NN) deg[n] = 0;     // re-zero for graph replay
        loc[i] = sum;
        sum += d;
    }
    part[tid] = sum;
    __syncthreads();
    for (int o = 1; o < 1024; o <<= 1) {
        int v = (tid >= o) ? part[tid - o] : 0;
        __syncthreads();
        part[tid] += v;
        __syncthreads();
    }
    int myoff = tid ? part[tid - 1] : 0;
#pragma unroll
    for (int i = 0; i < 20; i++) {
        int n = base + i;
        if (n <= NN) {
            int o = myoff + loc[i];
            off[n] = o;
            if (n < NN) cur[n] = o;
        }
    }
}

__device__ void do_select(int t, const float* __restrict__ embs) {
    int tid = threadIdx.x;   // 1024
    __shared__ int part[1024];
    __shared__ int sB, sAbove;
    __shared__ unsigned cnt_gt, cnt_cand;
    __shared__ unsigned sel_ord[DOUT];
    __shared__ int sel_idx[DOUT];
    __shared__ unsigned cand_ord[512];
    __shared__ int cand_idx[512];
    __shared__ int sh_idx[DOUT];
    __shared__ float sh_tanh[DOUT];

    const float* scores = g_scores + t * NN;
    int* hist = g_hist + t * 4096;

    int cnt[4];
    int s = 0;
#pragma unroll
    for (int j = 0; j < 4; j++) {
        int bin = 4095 - (tid * 4 + j);
        cnt[j] = hist[bin];
        s += cnt[j];
    }
    part[tid] = s;
    if (tid == 0) { cnt_gt = 0; cnt_cand = 0; }
    __syncthreads();
    for (int o = 1; o < 1024; o <<= 1) {
        int v = (tid >= o) ? part[tid - o] : 0;
        __syncthreads();
        part[tid] += v;
        __syncthreads();
    }
    int c = tid ? part[tid - 1] : 0;
#pragma unroll
    for (int j = 0; j < 4; j++) {
        int bin = 4095 - (tid * 4 + j);
        if (c < DOUT && c + cnt[j] >= DOUT) { sB = bin; sAbove = c; }
        c += cnt[j];
    }
    __syncthreads();
    // re-zero hist for next graph replay (reads are complete)
#pragma unroll
    for (int j = 0; j < 4; j++) hist[4095 - (tid * 4 + j)] = 0;
    int B = sB, above = sAbove, kneed = DOUT - above;

    for (int n = tid; n < NN; n += 1024) {
        unsigned ord = ord_of(scores[n]);
        int bucket = ord >> 20;
        if (bucket > B) {
            unsigned pos = atomicAdd(&cnt_gt, 1u);
            sel_ord[pos] = ord; sel_idx[pos] = n;
        } else if (bucket == B) {
            unsigned pos = atomicAdd(&cnt_cand, 1u);
            if (pos < 512) { cand_ord[pos] = ord; cand_idx[pos] = n; }
        }
    }
    __syncthreads();
    int nc = (int)cnt_cand; if (nc > 512) nc = 512;
    for (int ci = tid; ci < nc; ci += 1024) {
        unsigned mo = cand_ord[ci];
        int mi = cand_idx[ci];
        int r = 0;
        for (int j = 0; j < nc; j++) {
            unsigned o = cand_ord[j];
            r += (o > mo) || (o == mo && cand_idx[j] < mi);
        }
        if (r < kneed) { sel_ord[above + r] = mo; sel_idx[above + r] = mi; }
    }
    __syncthreads();
    if (tid < DOUT) {
        unsigned mo = sel_ord[tid];
        int mi = sel_idx[tid];
        int r = 0;
#pragma unroll 4
        for (int i = 0; i < DOUT; i++) {
            unsigned o = sel_ord[i];
            r += (o > mo) || (o == mo && sel_idx[i] < mi);
        }
        sh_idx[r] = mi;
        sh_tanh[r] = tanhf(scores[mi]);
    }
    __syncthreads();
    float* xt = g_xt + t * MAT;
    for (int e = tid; e < MAT; e += 1024) {
        int j = e >> 8;
        int d = e & 255;
        xt[d * DOUT + j] = embs[((size_t)t * NN + sh_idx[j]) * DIN + d] * sh_tanh[j];
    }
}

__global__ void mid2s_kernel(const float* __restrict__ embs) {
    if (blockIdx.x < TT) do_select(blockIdx.x, embs);
    else                 do_scan(blockIdx.x - TT);
}

// ================= small GEMM: 16x128 tile, K=256, up to 3 A-mats sharing B ===
#define KT 32
template <int NMAT>
__device__ __forceinline__ void gemm16(const float* __restrict__ AT0,
                                       const float* __restrict__ AT1,
                                       const float* __restrict__ AT2,
                                       const float* __restrict__ Bmat,
                                       int i0, ull a0[4], ull a1[4], ull a2[4],
                                       char* sm) {
    float (*Bs)[128] = (float(*)[128])sm;
    float (*As)[16]  = (float(*)[16])(sm + KT * 128 * 4);
    int tid = threadIdx.x;           // 256
    int ti = tid & 15, tj = tid >> 4;
    int brow = tid >> 5, bcol = (tid & 31) * 4;
    int akk = tid >> 4, aii = tid & 15;

    float4 pb[4];
    float pa0[2], pa1[2], pa2[2];
#pragma unroll
    for (int l = 0; l < 4; l++)
        pb[l] = *(const float4*)&Bmat[(brow + 8 * l) * 128 + bcol];
#pragma unroll
    for (int l = 0; l < 2; l++) {
        int kk = akk + 16 * l;
        pa0[l] = AT0[kk * DIN + i0 + aii];
        if (NMAT > 1) pa1[l] = AT1[kk * DIN + i0 + aii];
        if (NMAT > 2) pa2[l] = AT2[kk * DIN + i0 + aii];
    }
    for (int k0 = 0; k0 < DIN; k0 += KT) {
#pragma unroll
        for (int l = 0; l < 4; l++)
            *(float4*)&Bs[brow + 8 * l][bcol] = pb[l];
#pragma unroll
        for (int l = 0; l < 2; l++) {
            int kk = akk + 16 * l;
            As[0 * KT + kk][aii] = pa0[l];
            if (NMAT > 1) As[1 * KT + kk][aii] = pa1[l];
            if (NMAT > 2) As[2 * KT + kk][aii] = pa2[l];
        }
        __syncthreads();
        int kn = k0 + KT;
        if (kn < DIN) {
#pragma unroll
            for (int l = 0; l < 4; l++)
                pb[l] = *(const float4*)&Bmat[(kn + brow + 8 * l) * 128 + bcol];
#pragma unroll
            for (int l = 0; l < 2; l++) {
                int kk = kn + akk + 16 * l;
                pa0[l] = AT0[kk * DIN + i0 + aii];
                if (NMAT > 1) pa1[l] = AT1[kk * DIN + i0 + aii];
                if (NMAT > 2) pa2[l] = AT2[kk * DIN + i0 + aii];
            }
        }
#pragma unroll
        for (int kk = 0; kk < KT; kk++) {
            ull b[4];
            b[0] = *(const ull*)&Bs[kk][tj * 8 + 0];
            b[1] = *(const ull*)&Bs[kk][tj * 8 + 2];
            b[2] = *(const ull*)&Bs[kk][tj * 8 + 4];
            b[3] = *(const ull*)&Bs[kk][tj * 8 + 6];
            {
                ull av = dup2(As[0 * KT + kk][ti]);
#pragma unroll
                for (int j = 0; j < 4; j++)
                    asm("fma.rn.f32x2 %0, %1, %2, %0;" : "+l"(a0[j]) : "l"(av), "l"(b[j]));
            }
            if (NMAT > 1) {
                ull av = dup2(As[1 * KT + kk][ti]);
#pragma unroll
                for (int j = 0; j < 4; j++)
                    asm("fma.rn.f32x2 %0, %1, %2, %0;" : "+l"(a1[j]) : "l"(av), "l"(b[j]));
            }
            if (NMAT > 2) {
                ull av = dup2(As[2 * KT + kk][ti]);
#pragma unroll
                for (int j = 0; j < 4; j++)
                    asm("fma.rn.f32x2 %0, %1, %2, %0;" : "+l"(a2[j]) : "l"(av), "l"(b[j]));
            }
        }
        __syncthreads();
    }
}

// ---- gruA: z = sig(WXz + Uz@W + bz), r = sig(WXr + Ur@W + br), rW = r*W ------
__device__ __forceinline__ void dev_gruA(int t, int bx,
                                         const float* __restrict__ bz,
                                         const float* __restrict__ br,
                                         char* sm) {
    int i0 = bx * 16;
    ull a0[4] = {0, 0, 0, 0}, a1[4] = {0, 0, 0, 0};
    gemm16<2>(g_WT + 1 * MSQ, g_WT + 3 * MSQ, (const float*)0,
              g_Wn + t * MAT, i0, a0, a1, a0, sm);
    int ti = threadIdx.x & 15, tj = threadIdx.x >> 4;
    int row = i0 + ti, col = tj * 8;
    const float* WXz = g_WX + (0 * TT + t) * MAT;
    const float* WXr = g_WX + (1 * TT + t) * MAT;
    const float* Wt  = g_Wn + t * MAT;
#pragma unroll
    for (int j = 0; j < 4; j++) {
        int o = row * DOUT + col + 2 * j;
        float2 az = upk(a0[j]), ar = upk(a1[j]);
        float2 xz = *(const float2*)&WXz[o];
        float2 xr = *(const float2*)&WXr[o];
        float2 vz = *(const float2*)&bz[o];
        float2 vr = *(const float2*)&br[o];
        float2 wv = *(const float2*)&Wt[o];
        float2 z2, rw2;
        z2.x = sigmoidf_(az.x + xz.x + vz.x);
        z2.y = sigmoidf_(az.y + xz.y + vz.y);
        rw2.x = sigmoidf_(ar.x + xr.x + vr.x) * wv.x;
        rw2.y = sigmoidf_(ar.y + xr.y + vr.y) * wv.y;
        *(float2*)&g_z[o] = z2;
        *(float2*)&g_rW[o] = rw2;
    }
}

// ---- gruB: h = tanh(WXh + Uh@rW + bh); Wn_{t+1} = W + z*(h - W); fp16 copy ---
__global__ void gruB_kernel(int t, const float* __restrict__ bh) {
    __shared__ __align__(16) char sm[KT * 128 * 4 + KT * 16 * 4];
    int i0 = blockIdx.x * 16;
    ull a0[4] = {0, 0, 0, 0};
    gemm16<1>(g_WT + 5 * MSQ, (const float*)0, (const float*)0,
              g_rW, i0, a0, a0, a0, sm);
    int ti = threadIdx.x & 15, tj = threadIdx.x >> 4;
    int row = i0 + ti, col = tj * 8;
    const float* WXh = g_WX + (2 * TT + t) * MAT;
    const float* Wt  = g_Wn + t * MAT;
    float* Wnx = g_Wn + (t + 1) * MAT;
    __half* Whx = g_Wh + t * MAT;
#pragma unroll
    for (int j = 0; j < 4; j++) {
        int o = row * DOUT + col + 2 * j;
        float2 ah = upk(a0[j]);
        float2 xh = *(const float2*)&WXh[o];
        float2 vh = *(const float2*)&bh[o];
        float2 wv = *(const float2*)&Wt[o];
        float2 z2 = *(const float2*)&g_z[o];
        float hx = tanhf(ah.x + xh.x + vh.x);
        float hy = tanhf(ah.y + xh.y + vh.y);
        float2 wn;
        wn.x = wv.x + z2.x * (hx - wv.x);
        wn.y = wv.y + z2.y * (hy - wv.y);
        *(float2*)&Wnx[o] = wn;
        *(__half2*)&Whx[o] = __float22half2_rn(wn);
    }
}

// ---- CSR fill body (2500 blocks per t) ---------------------------------------
__device__ __forceinline__ void dev_fill(int t, int bx,
                                         const int* __restrict__ ei,
                                         const float* __restrict__ w) {
    int e = bx * 256 + threadIdx.x;
    const int* dst = ei + (size_t)t * 2 * EE;
    const int* src = dst + EE;
    int d = dst[e];
    int pos = atomicAdd(&g_cur[t * NN + d], 1);
    g_csr[(size_t)t * EE + pos] = make_int2(src[e], __float_as_int(w[(size_t)t * EE + e]));
}

// ================= wxfill: WX GEMMs (64 blocks) | fill(0) (2500) ==============
__global__ void wxfill_kernel(const int* __restrict__ ei, const float* __restrict__ w) {
    int b = blockIdx.x;
    if (b < 64) {
        __shared__ __align__(16) char sm[KT * 128 * 4 + 3 * KT * 16 * 4];
        int t = b >> 4, i0 = (b & 15) * 16;
        ull a0[4] = {0, 0, 0, 0}, a1[4] = {0, 0, 0, 0}, a2[4] = {0, 0, 0, 0};
        gemm16<3>(g_WT + 0 * MSQ, g_WT + 2 * MSQ, g_WT + 4 * MSQ,
                  g_xt + t * MAT, i0, a0, a1, a2, sm);
        int ti = threadIdx.x & 15, tj = threadIdx.x >> 4;
        int base = (i0 + ti) * DOUT + tj * 8;
#pragma unroll
        for (int j = 0; j < 4; j++) {
            *(ull*)&g_WX[(0 * TT + t) * MAT + base + 2 * j] = a0[j];
            *(ull*)&g_WX[(1 * TT + t) * MAT + base + 2 * j] = a1[j];
            *(ull*)&g_WX[(2 * TT + t) * MAT + base + 2 * j] = a2[j];
        }
    } else {
        dev_fill(0, b - 64, ei, w);
    }
}

// ================= tensor-core sgemm: y_t = xh_t @ Wh_t (fp16 in, fp32 acc) ===
#define BM 64
#define BN 128
#define SGB ((NN + BM - 1) / BM)   // 313
#define ASTRIDE 40                  // halves; 80B rows -> 5r mod 8 ldmatrix-clean
#define BSTRIDE 136                 // halves; 272B rows -> r mod 8 ldmatrix-clean
#define SGEMM_SMEM (64 * ASTRIDE * 2 + 32 * BSTRIDE * 2)   // 13824

__device__ __forceinline__ void dev_sgemm(int t, int bx, char* sm) {
    __half* Ah = (__half*)sm;                       // [64][ASTRIDE]
    __half* Bh = (__half*)(sm + 64 * ASTRIDE * 2);  // [32][BSTRIDE]
    const __half* A = g_xh + (size_t)t * NN * DIN;
    const __half* B = g_Wh + t * MAT;               // Wn(t+1) fp16 [256][128]
    __half* C = g_y + (size_t)t * NN * DOUT;
    int tid = threadIdx.x, lane = tid & 31, wid = tid >> 5;
    int wm = wid >> 2, wq = wid & 3;                // warp tile: rows wm*32, cols wq*32
    int bm = bx * BM;

    float c[2][4][4];
#pragma unroll
    for (int ma = 0; ma < 2; ma++)
#pragma unroll
        for (int na = 0; na < 4; na++)
#pragma unroll
            for (int i = 0; i < 4; i++) c[ma][na][i] = 0.0f;

    int arow = tid >> 2, acol = (tid & 3) * 8;
    int agr = bm + arow;
    uint4 zero4 = make_uint4(0, 0, 0, 0);

    for (int k0 = 0; k0 < DIN; k0 += 32) {
        uint4 av = (agr < NN) ? *(const uint4*)&A[(size_t)agr * DIN + k0 + acol] : zero4;
        *(uint4*)&Ah[arow * ASTRIDE + acol] = av;
#pragma unroll
        for (int pp = 0; pp < 2; pp++) {
            int q = tid + pp * 256;
            int brr = q >> 4, bcc = (q & 15) * 8;
            *(uint4*)&Bh[brr * BSTRIDE + bcc] = *(const uint4*)&B[(k0 + brr) * BN + bcc];
        }
        __syncthreads();
#pragma unroll
        for (int ks = 0; ks < 32; ks += 16) {
            unsigned bf[4][2];
#pragma unroll
            for (int na = 0; na < 4; na++) {
                int r = ks + (lane & 15);
                unsigned ad = smaddr(&Bh[r * BSTRIDE + wq * 32 + na * 8]);
                asm volatile("ldmatrix.sync.aligned.m8n8.x2.trans.shared.b16 {%0,%1}, [%2];"
                             : "=r"(bf[na][0]), "=r"(bf[na][1]) : "r"(ad));
            }
#pragma unroll
            for (int ma = 0; ma < 2; ma++) {
                int mr = wm * 32 + ma * 16 + (lane & 15);
                int kc = ks + ((lane >> 4) << 3);
                unsigned ad = smaddr(&Ah[mr * ASTRIDE + kc]);
                unsigned a0, a1, a2, a3;
                asm volatile("ldmatrix.sync.aligned.m8n8.x4.shared.b16 {%0,%1,%2,%3}, [%4];"
                             : "=r"(a0), "=r"(a1), "=r"(a2), "=r"(a3) : "r"(ad));
#pragma unroll
                for (int na = 0; na < 4; na++) {
                    asm volatile(
                        "mma.sync.aligned.m16n8k16.row.col.f32.f16.f16.f32 "
                        "{%0,%1,%2,%3}, {%4,%5,%6,%7}, {%8,%9}, {%0,%1,%2,%3};"
                        : "+f"(c[ma][na][0]), "+f"(c[ma][na][1]),
                          "+f"(c[ma][na][2]), "+f"(c[ma][na][3])
                        : "r"(a0), "r"(a1), "r"(a2), "r"(a3),
                          "r"(bf[na][0]), "r"(bf[na][1]));
                }
            }
        }
        __syncthreads();
    }
#pragma unroll
    for (int ma = 0; ma < 2; ma++) {
        int row0 = bm + wm * 32 + ma * 16 + (lane >> 2);
#pragma unroll
        for (int na = 0; na < 4; na++) {
            int col = wq * 32 + na * 8 + (lane & 3) * 2;
            if (row0 < NN)
                *(__half2*)&C[(size_t)row0 * DOUT + col] =
                    __floats2half2_rn(c[ma][na][0], c[ma][na][1]);
            if (row0 + 8 < NN)
                *(__half2*)&C[(size_t)(row0 + 8) * DOUT + col] =
                    __floats2half2_rn(c[ma][na][2], c[ma][na][3]);
        }
    }
}

__device__ __forceinline__ void dev_gather(int t, int bx, float* __restrict__ out) {
    int node = bx * 8 + (threadIdx.x >> 5);
    int lane = threadIdx.x & 31;
    const int* off = g_off + t * (NN + 1);
    const int2* csr = g_csr + (size_t)t * EE;
    const __half* y = g_y + (size_t)t * NN * DOUT;
    int beg = off[node], end = off[node + 1];
    float4 acc = make_float4(0.f, 0.f, 0.f, 0.f);
    int e = beg;
    for (; e + 4 <= end; e += 4) {
        int2 c0 = csr[e + 0], c1 = csr[e + 1], c2 = csr[e + 2], c3 = csr[e + 3];
        uint2 r0 = *(const uint2*)&y[(size_t)c0.x * DOUT + lane * 4];
        uint2 r1 = *(const uint2*)&y[(size_t)c1.x * DOUT + lane * 4];
        uint2 r2 = *(const uint2*)&y[(size_t)c2.x * DOUT + lane * 4];
        uint2 r3 = *(const uint2*)&y[(size_t)c3.x * DOUT + lane * 4];
        float w0 = __int_as_float(c0.y), w1 = __int_as_float(c1.y);
        float w2 = __int_as_float(c2.y), w3 = __int_as_float(c3.y);
        float2 a0 = __half22float2(*(__half2*)&r0.x), b0 = __half22float2(*(__half2*)&r0.y);
        float2 a1 = __half22float2(*(__half2*)&r1.x), b1 = __half22float2(*(__half2*)&r1.y);
        float2 a2 = __half22float2(*(__half2*)&r2.x), b2 = __half22float2(*(__half2*)&r2.y);
        float2 a3 = __half22float2(*(__half2*)&r3.x), b3 = __half22float2(*(__half2*)&r3.y);
        acc.x += w0 * a0.x + w1 * a1.x + w2 * a2.x + w3 * a3.x;
        acc.y += w0 * a0.y + w1 * a1.y + w2 * a2.y + w3 * a3.y;
        acc.z += w0 * b0.x + w1 * b1.x + w2 * b2.x + w3 * b3.x;
        acc.w += w0 * b0.y + w1 * b1.y + w2 * b2.y + w3 * b3.y;
    }
    for (; e < end; e++) {
        int2 c0 = csr[e];
        float w0 = __int_as_float(c0.y);
        uint2 r0 = *(const uint2*)&y[(size_t)c0.x * DOUT + lane * 4];
        float2 a0 = __half22float2(*(__half2*)&r0.x), b0 = __half22float2(*(__half2*)&r0.y);
        acc.x += w0 * a0.x; acc.y += w0 * a0.y; acc.z += w0 * b0.x; acc.w += w0 * b0.y;
    }
    acc.x = (acc.x >= 0.f) ? acc.x : SLOPE * acc.x;
    acc.y = (acc.y >= 0.f) ? acc.y : SLOPE * acc.y;
    acc.z = (acc.z >= 0.f) ? acc.z : SLOPE * acc.z;
    acc.w = (acc.w >= 0.f) ? acc.w : SLOPE * acc.w;
    *(float4*)&out[((size_t)t * NN + node) * DOUT + lane * 4] = acc;
}

// ==== pipe: [gruA(t_sg+1)] | sgemm(t_sg) | [fill(t_fill)] | [gather(t_ga)] ====
#define PIPE_SMEM (KT * 128 * 4 + 2 * KT * 16 * 4)   // 20480 >= SGEMM_SMEM
__global__ __launch_bounds__(256, 3)
void pipe_kernel(int t_sg, int t_ga, int t_fill, int ngru,
                 const int* __restrict__ ei, const float* __restrict__ w,
                 const float* __restrict__ bz, const float* __restrict__ br,
                 float* __restrict__ out) {
    __shared__ __align__(16) char sm[PIPE_SMEM];
    int b = blockIdx.x;
    if (b < ngru) { dev_gruA(t_sg + 1, b, bz, br, sm); return; }
    b -= ngru;
    if (b < SGB) { dev_sgemm(t_sg, b, sm); return; }
    b -= SGB;
    if (t_fill >= 0) {
        if (b < 2500) { dev_fill(t_fill, b, ei, w); return; }
        b -= 2500;
    }
    dev_gather(t_ga, b, out);
}

__global__ void gruA0_kernel(const float* __restrict__ bz, const float* __restrict__ br) {
    __shared__ __align__(16) char sm[KT * 128 * 4 + 2 * KT * 16 * 4];
    dev_gruA(0, blockIdx.x, bz, br, sm);
}

__global__ void gather_only_kernel(int t, float* __restrict__ out) {
    dev_gather(t, blockIdx.x, out);
}

// ---------------- launcher ----------------
extern "C" void kernel_launch(void* const* d_in, const int* in_sizes, int n_in,
                              void* d_out, int out_size) {
    const float* node_embs  = (const float*)d_in[0];
    const int*   edge_index = (const int*)d_in[1];
    const float* edge_w     = (const float*)d_in[2];
    const float* mask       = (const float*)d_in[3];
    const float* p          = (const float*)d_in[4];
    const float* Wz         = (const float*)d_in[5];
    const float* Uz         = (const float*)d_in[6];
    const float* bz         = (const float*)d_in[7];
    const float* Wr         = (const float*)d_in[8];
    const float* Ur         = (const float*)d_in[9];
    const float* br         = (const float*)d_in[10];
    const float* Wh         = (const float*)d_in[11];
    const float* Uh         = (const float*)d_in[12];
    const float* bh         = (const float*)d_in[13];
    const float* W0         = (const float*)d_in[14];
    float* out = (float*)d_out;

    front_kernel<<<FB_TOTAL, 256>>>(node_embs, p, mask, edge_index,
                                    Wz, Uz, Wr, Ur, Wh, Uh, W0);
    mid2s_kernel<<<2 * TT, 1024>>>(node_embs);
    wxfill_kernel<<<64 + 2500, 256>>>(edge_index, edge_w);

    gruA0_kernel<<<16, 256>>>(bz, br);
    gruB_kernel<<<16, 256>>>(0, bh);
    // P1: sgemm(0) + gruA(1) + fill(1)
    pipe_kernel<<<16 + SGB + 2500, 256>>>(0, -1, 1, 16,
                                          edge_index, edge_w, bz, br, out);
    gruB_kernel<<<16, 256>>>(1, bh);
    // P2: sgemm(1) + gruA(2) + fill(2) + gather(0)
    pipe_kernel<<<16 + SGB + 2500 + 2500, 256>>>(1, 0, 2, 16,
                                                 edge_index, edge_w, bz, br, out);
    gruB_kernel<<<16, 256>>>(2, bh);
    // P3: sgemm(2) + gruA(3) + fill(3) + gather(1)
    pipe_kernel<<<16 + SGB + 2500 + 2500, 256>>>(2, 1, 3, 16,
                                                 edge_index, edge_w, bz, br, out);
    gruB_kernel<<<16, 256>>>(3, bh);
    // P4: sgemm(3) + gather(2)
    pipe_kernel<<<SGB + 2500, 256>>>(3, 2, -1, 0,
                                     edge_index, edge_w, bz, br, out);
    gather_only_kernel<<<2500, 256>>>(3, out);
}

// round 8
// speedup vs baseline: 2.6056x; 1.1581x over previous
#include <cuda_runtime.h>
#include <cuda_fp16.h>

#define TT   4
#define NN   20000
#define EE   640000
#define DIN  256
#define DOUT 128
#define MAT  (DIN * DOUT)      // 32768
#define MSQ  (DIN * DIN)       // 65536
#define SLOPE 0.22916666666666666f

typedef unsigned long long ull;

// ---------------- scratch (__device__ globals; no allocation) ----------------
__device__ float  g_scores[TT * NN];
__device__ float  g_xt[TT * MAT];             // per-t [256][128]
__device__ float  g_Wn[(TT + 1) * MAT];       // W0 + evolved weights (fp32)
__device__ __half g_Wh[TT * MAT];             // Wn(t+1) fp16 for the y-GEMM
__device__ __half g_xh[(size_t)TT * NN * DIN];// fp16 copy of node_embs (41 MB)
__device__ float  g_WT[6 * MSQ];              // transposed Wz,Uz,Wr,Ur,Wh,Uh
__device__ float  g_WX[3 * TT * MAT];         // Wz@xt, Wr@xt, Wh@xt per t
__device__ float  g_z[MAT];
__device__ float  g_rW[MAT];
__device__ __half g_y[(size_t)TT * NN * DOUT];
__device__ int    g_deg[TT * NN];
__device__ int    g_off[TT * (NN + 1)];
__device__ int    g_cur[TT * NN];
__device__ int2   g_csr[(size_t)TT * EE];
__device__ int    g_hist[TT * 4096];          // zero-init; re-zeroed in select

// ---------------- helpers ----------------
__device__ __forceinline__ unsigned ord_of(float f) {
    unsigned b = __float_as_uint(f);
    return b ^ ((b & 0x80000000u) ? 0xFFFFFFFFu : 0x80000000u);
}
__device__ __forceinline__ float sigmoidf_(float x) {
    return 1.0f / (1.0f + expf(-x));
}
__device__ __forceinline__ float2 upk(ull v) {
    float2 r;
    asm("mov.b64 {%0, %1}, %2;" : "=f"(r.x), "=f"(r.y) : "l"(v));
    return r;
}
__device__ __forceinline__ ull dup2(float a) {
    ull r;
    asm("mov.b64 %0, {%1, %1};" : "=l"(r) : "f"(a));
    return r;
}
__device__ __forceinline__ unsigned smaddr(const void* p) {
    return (unsigned)__cvta_generic_to_shared(p);
}

// ================= L1: front = scores+hist+fp16copy | deg | prep =============
#define FB_SCORES 10000
#define FB_DEG    10000
#define FB_PREP   1664
#define FB_TOTAL  (FB_SCORES + FB_DEG + FB_PREP)

__global__ void front_kernel(const float* __restrict__ embs,
                             const float* __restrict__ p,
                             const float* __restrict__ mask,
                             const int* __restrict__ ei,
                             const float* __restrict__ Wz, const float* __restrict__ Uz,
                             const float* __restrict__ Wr, const float* __restrict__ Ur,
                             const float* __restrict__ Wh, const float* __restrict__ Uh,
                             const float* __restrict__ W0) {
    int b = blockIdx.x;
    int tid = threadIdx.x;
    if (b < FB_SCORES) {
        __shared__ float sp[DIN];
        sp[tid] = p[tid];
        __syncthreads();
        int t = b / 2500;
        int warp = tid >> 5, lane = tid & 31;
        int n = (b % 2500) * 8 + warp;
        const float* xr = embs + ((size_t)t * NN + n) * DIN;
        float4 x0 = *(const float4*)&xr[lane * 4];
        float4 x1 = *(const float4*)&xr[128 + lane * 4];
        __half* xh = g_xh + ((size_t)t * NN + n) * DIN;
        *(__half2*)&xh[lane * 4]           = __floats2half2_rn(x0.x, x0.y);
        *(__half2*)&xh[lane * 4 + 2]       = __floats2half2_rn(x0.z, x0.w);
        *(__half2*)&xh[128 + lane * 4]     = __floats2half2_rn(x1.x, x1.y);
        *(__half2*)&xh[128 + lane * 4 + 2] = __floats2half2_rn(x1.z, x1.w);
        float4 p0 = *(const float4*)&sp[lane * 4];
        float4 p1 = *(const float4*)&sp[128 + lane * 4];
        float s = x0.x * p0.x + x0.y * p0.y + x0.z * p0.z + x0.w * p0.w
                + x1.x * p1.x + x1.y * p1.y + x1.z * p1.z + x1.w * p1.w;
        float q = p0.x * p0.x + p0.y * p0.y + p0.z * p0.z + p0.w * p0.w
                + p1.x * p1.x + p1.y * p1.y + p1.z * p1.z + p1.w * p1.w;
#pragma unroll
        for (int o = 16; o > 0; o >>= 1) {
            s += __shfl_down_sync(0xFFFFFFFFu, s, o);
            q += __shfl_down_sync(0xFFFFFFFFu, q, o);
        }
        if (lane == 0) {
            float sc = s * rsqrtf(q) + mask[t * NN + n];
            g_scores[t * NN + n] = sc;
            atomicAdd(&g_hist[t * 4096 + (ord_of(sc) >> 20)], 1);
        }
    } else if (b < FB_SCORES + FB_DEG) {
        int idx = b - FB_SCORES;
        int t = idx / 2500;
        int e = (idx % 2500) * 256 + tid;
        const int* dst = ei + (size_t)t * 2 * EE;
        atomicAdd(&g_deg[t * NN + dst[e]], 1);
    } else {
        int idx = (b - FB_SCORES - FB_DEG) * 256 + tid;
        const float* srcs[6] = {Wz, Uz, Wr, Ur, Wh, Uh};
        if (idx < 6 * MSQ) {
            int m = idx >> 16;
            int e = idx & 0xFFFF;
            int k = e >> 8, i = e & 255;
            g_WT[idx] = srcs[m][i * DIN + k];
        } else {
            int e = idx - 6 * MSQ;
            g_Wn[e] = W0[e];
        }
    }
}

// ================= L2: mid2s = select+xt (blocks 0-3) | scan (blocks 4-7) =====
__device__ void do_scan(int t) {
    __shared__ int part[1024];
    int tid = threadIdx.x;
    int* deg = g_deg + t * NN;
    int* off = g_off + t * (NN + 1);
    int* cur = g_cur + t * NN;
    int base = tid * 20;
    int loc[20];
    int sum = 0;
#pragma unroll
    for (int i = 0; i < 20; i++) {
        int n = base + i;
        int d = (n < NN) ? deg[n] : 0;
        if (n < NN) deg[n] = 0;
        loc[i] = sum;
        sum += d;
    }
    part[tid] = sum;
    __syncthreads();
    for (int o = 1; o < 1024; o <<= 1) {
        int v = (tid >= o) ? part[tid - o] : 0;
        __syncthreads();
        part[tid] += v;
        __syncthreads();
    }
    int myoff = tid ? part[tid - 1] : 0;
#pragma unroll
    for (int i = 0; i < 20; i++) {
        int n = base + i;
        if (n <= NN) {
            int o = myoff + loc[i];
            off[n] = o;
            if (n < NN) cur[n] = o;
        }
    }
}

__device__ void do_select(int t, const float* __restrict__ embs) {
    int tid = threadIdx.x;   // 1024
    __shared__ int part[1024];
    __shared__ int sB, sAbove;
    __shared__ unsigned cnt_gt, cnt_cand;
    __shared__ unsigned sel_ord[DOUT];
    __shared__ int sel_idx[DOUT];
    __shared__ unsigned cand_ord[512];
    __shared__ int cand_idx[512];
    __shared__ int sh_idx[DOUT];
    __shared__ float sh_tanh[DOUT];

    const float* scores = g_scores + t * NN;
    int* hist = g_hist + t * 4096;

    int cnt[4];
    int s = 0;
#pragma unroll
    for (int j = 0; j < 4; j++) {
        int bin = 4095 - (tid * 4 + j);
        cnt[j] = hist[bin];
        s += cnt[j];
    }
    part[tid] = s;
    if (tid == 0) { cnt_gt = 0; cnt_cand = 0; }
    __syncthreads();
    for (int o = 1; o < 1024; o <<= 1) {
        int v = (tid >= o) ? part[tid - o] : 0;
        __syncthreads();
        part[tid] += v;
        __syncthreads();
    }
    int c = tid ? part[tid - 1] : 0;
#pragma unroll
    for (int j = 0; j < 4; j++) {
        int bin = 4095 - (tid * 4 + j);
        if (c < DOUT && c + cnt[j] >= DOUT) { sB = bin; sAbove = c; }
        c += cnt[j];
    }
    __syncthreads();
#pragma unroll
    for (int j = 0; j < 4; j++) hist[4095 - (tid * 4 + j)] = 0;
    int B = sB, above = sAbove, kneed = DOUT - above;

    for (int n = tid; n < NN; n += 1024) {
        unsigned ord = ord_of(scores[n]);
        int bucket = ord >> 20;
        if (bucket > B) {
            unsigned pos = atomicAdd(&cnt_gt, 1u);
            sel_ord[pos] = ord; sel_idx[pos] = n;
        } else if (bucket == B) {
            unsigned pos = atomicAdd(&cnt_cand, 1u);
            if (pos < 512) { cand_ord[pos] = ord; cand_idx[pos] = n; }
        }
    }
    __syncthreads();
    int nc = (int)cnt_cand; if (nc > 512) nc = 512;
    for (int ci = tid; ci < nc; ci += 1024) {
        unsigned mo = cand_ord[ci];
        int mi = cand_idx[ci];
        int r = 0;
        for (int j = 0; j < nc; j++) {
            unsigned o = cand_ord[j];
            r += (o > mo) || (o == mo && cand_idx[j] < mi);
        }
        if (r < kneed) { sel_ord[above + r] = mo; sel_idx[above + r] = mi; }
    }
    __syncthreads();
    if (tid < DOUT) {
        unsigned mo = sel_ord[tid];
        int mi = sel_idx[tid];
        int r = 0;
#pragma unroll 4
        for (int i = 0; i < DOUT; i++) {
            unsigned o = sel_ord[i];
            r += (o > mo) || (o == mo && sel_idx[i] < mi);
        }
        sh_idx[r] = mi;
        sh_tanh[r] = tanhf(scores[mi]);
    }
    __syncthreads();
    float* xt = g_xt + t * MAT;
    for (int e = tid; e < MAT; e += 1024) {
        int j = e >> 8;
        int d = e & 255;
        xt[d * DOUT + j] = embs[((size_t)t * NN + sh_idx[j]) * DIN + d] * sh_tanh[j];
    }
}

__global__ void mid2s_kernel(const float* __restrict__ embs) {
    if (blockIdx.x < TT) do_select(blockIdx.x, embs);
    else                 do_scan(blockIdx.x - TT);
}

// ===== small GEMM: 8x128 tile, K=256, up to 3 A-mats sharing B (256 thr) ======
#define KT 32
template <int NMAT>
__device__ __forceinline__ void gemmR8(const float* __restrict__ AT0,
                                       const float* __restrict__ AT1,
                                       const float* __restrict__ AT2,
                                       const float* __restrict__ Bmat,
                                       int i0, ull a0[2], ull a1[2], ull a2[2],
                                       char* sm) {
    float (*Bs)[128] = (float(*)[128])sm;                // 16 KB
    float (*As)[8]   = (float(*)[8])(sm + KT * 128 * 4); // NMAT*32*8 floats
    int tid = threadIdx.x;           // 256
    int ti = tid & 7, tj = tid >> 3;                 // tj: 0..31 (4 cols each)
    int brow = tid >> 5, bcol = (tid & 31) * 4;
    int akk = tid >> 3, aii = tid & 7;               // A load: one elem per mat

    float4 pb[4];
    float pa0, pa1, pa2;
#pragma unroll
    for (int l = 0; l < 4; l++)
        pb[l] = *(const float4*)&Bmat[(brow + 8 * l) * 128 + bcol];
    pa0 = AT0[akk * DIN + i0 + aii];
    if (NMAT > 1) pa1 = AT1[akk * DIN + i0 + aii];
    if (NMAT > 2) pa2 = AT2[akk * DIN + i0 + aii];

    for (int k0 = 0; k0 < DIN; k0 += KT) {
#pragma unroll
        for (int l = 0; l < 4; l++)
            *(float4*)&Bs[brow + 8 * l][bcol] = pb[l];
        As[0 * KT + akk][aii] = pa0;
        if (NMAT > 1) As[1 * KT + akk][aii] = pa1;
        if (NMAT > 2) As[2 * KT + akk][aii] = pa2;
        __syncthreads();
        int kn = k0 + KT;
        if (kn < DIN) {
#pragma unroll
            for (int l = 0; l < 4; l++)
                pb[l] = *(const float4*)&Bmat[(kn + brow + 8 * l) * 128 + bcol];
            pa0 = AT0[(kn + akk) * DIN + i0 + aii];
            if (NMAT > 1) pa1 = AT1[(kn + akk) * DIN + i0 + aii];
            if (NMAT > 2) pa2 = AT2[(kn + akk) * DIN + i0 + aii];
        }
#pragma unroll
        for (int kk = 0; kk < KT; kk++) {
            ull b0 = *(const ull*)&Bs[kk][tj * 4 + 0];
            ull b1 = *(const ull*)&Bs[kk][tj * 4 + 2];
            {
                ull av = dup2(As[0 * KT + kk][ti]);
                asm("fma.rn.f32x2 %0, %1, %2, %0;" : "+l"(a0[0]) : "l"(av), "l"(b0));
                asm("fma.rn.f32x2 %0, %1, %2, %0;" : "+l"(a0[1]) : "l"(av), "l"(b1));
            }
            if (NMAT > 1) {
                ull av = dup2(As[1 * KT + kk][ti]);
                asm("fma.rn.f32x2 %0, %1, %2, %0;" : "+l"(a1[0]) : "l"(av), "l"(b0));
                asm("fma.rn.f32x2 %0, %1, %2, %0;" : "+l"(a1[1]) : "l"(av), "l"(b1));
            }
            if (NMAT > 2) {
                ull av = dup2(As[2 * KT + kk][ti]);
                asm("fma.rn.f32x2 %0, %1, %2, %0;" : "+l"(a2[0]) : "l"(av), "l"(b0));
                asm("fma.rn.f32x2 %0, %1, %2, %0;" : "+l"(a2[1]) : "l"(av), "l"(b1));
            }
        }
        __syncthreads();
    }
}

// ---- gruA (32 blocks): z = sig(WXz+Uz@W+bz), r = sig(WXr+Ur@W+br), rW = r*W --
__device__ __forceinline__ void dev_gruA(int t, int bx,
                                         const float* __restrict__ bz,
                                         const float* __restrict__ br,
                                         char* sm) {
    int i0 = bx * 8;
    ull a0[2] = {0, 0}, a1[2] = {0, 0};
    gemmR8<2>(g_WT + 1 * MSQ, g_WT + 3 * MSQ, (const float*)0,
              g_Wn + t * MAT, i0, a0, a1, a0, sm);
    int ti = threadIdx.x & 7, tj = threadIdx.x >> 3;
    int row = i0 + ti, col = tj * 4;
    const float* WXz = g_WX + (0 * TT + t) * MAT;
    const float* WXr = g_WX + (1 * TT + t) * MAT;
    const float* Wt  = g_Wn + t * MAT;
#pragma unroll
    for (int j = 0; j < 2; j++) {
        int o = row * DOUT + col + 2 * j;
        float2 az = upk(a0[j]), ar = upk(a1[j]);
        float2 xz = *(const float2*)&WXz[o];
        float2 xr = *(const float2*)&WXr[o];
        float2 vz = *(const float2*)&bz[o];
        float2 vr = *(const float2*)&br[o];
        float2 wv = *(const float2*)&Wt[o];
        float2 z2, rw2;
        z2.x = sigmoidf_(az.x + xz.x + vz.x);
        z2.y = sigmoidf_(az.y + xz.y + vz.y);
        rw2.x = sigmoidf_(ar.x + xr.x + vr.x) * wv.x;
        rw2.y = sigmoidf_(ar.y + xr.y + vr.y) * wv.y;
        *(float2*)&g_z[o] = z2;
        *(float2*)&g_rW[o] = rw2;
    }
}

// ---- gruB (32 blocks): h = tanh(WXh+Uh@rW+bh); Wn_{t+1} = W + z*(h-W) -------
__global__ void gruB_kernel(int t, const float* __restrict__ bh) {
    __shared__ __align__(16) char sm[KT * 128 * 4 + KT * 8 * 4];
    int i0 = blockIdx.x * 8;
    ull a0[2] = {0, 0};
    gemmR8<1>(g_WT + 5 * MSQ, (const float*)0, (const float*)0,
              g_rW, i0, a0, a0, a0, sm);
    int ti = threadIdx.x & 7, tj = threadIdx.x >> 3;
    int row = i0 + ti, col = tj * 4;
    const float* WXh = g_WX + (2 * TT + t) * MAT;
    const float* Wt  = g_Wn + t * MAT;
    float* Wnx = g_Wn + (t + 1) * MAT;
    __half* Whx = g_Wh + t * MAT;
#pragma unroll
    for (int j = 0; j < 2; j++) {
        int o = row * DOUT + col + 2 * j;
        float2 ah = upk(a0[j]);
        float2 xh = *(const float2*)&WXh[o];
        float2 vh = *(const float2*)&bh[o];
        float2 wv = *(const float2*)&Wt[o];
        float2 z2 = *(const float2*)&g_z[o];
        float hx = tanhf(ah.x + xh.x + vh.x);
        float hy = tanhf(ah.y + xh.y + vh.y);
        float2 wn;
        wn.x = wv.x + z2.x * (hx - wv.x);
        wn.y = wv.y + z2.y * (hy - wv.y);
        *(float2*)&Wnx[o] = wn;
        *(__half2*)&Whx[o] = __float22half2_rn(wn);
    }
}

// ---- CSR fill body (2500 blocks per t) ---------------------------------------
__device__ __forceinline__ void dev_fill(int t, int bx,
                                         const int* __restrict__ ei,
                                         const float* __restrict__ w) {
    int e = bx * 256 + threadIdx.x;
    const int* dst = ei + (size_t)t * 2 * EE;
    const int* src = dst + EE;
    int d = dst[e];
    int pos = atomicAdd(&g_cur[t * NN + d], 1);
    g_csr[(size_t)t * EE + pos] = make_int2(src[e], __float_as_int(w[(size_t)t * EE + e]));
}

// ================= wxfill: WX GEMMs (128 blocks) | fill(0) (2500) =============
__global__ void wxfill_kernel(const int* __restrict__ ei, const float* __restrict__ w) {
    int b = blockIdx.x;
    if (b < 128) {
        __shared__ __align__(16) char sm[KT * 128 * 4 + 3 * KT * 8 * 4];
        int t = b >> 5, i0 = (b & 31) * 8;
        ull a0[2] = {0, 0}, a1[2] = {0, 0}, a2[2] = {0, 0};
        gemmR8<3>(g_WT + 0 * MSQ, g_WT + 2 * MSQ, g_WT + 4 * MSQ,
                  g_xt + t * MAT, i0, a0, a1, a2, sm);
        int ti = threadIdx.x & 7, tj = threadIdx.x >> 3;
        int base = (i0 + ti) * DOUT + tj * 4;
#pragma unroll
        for (int j = 0; j < 2; j++) {
            *(ull*)&g_WX[(0 * TT + t) * MAT + base + 2 * j] = a0[j];
            *(ull*)&g_WX[(1 * TT + t) * MAT + base + 2 * j] = a1[j];
            *(ull*)&g_WX[(2 * TT + t) * MAT + base + 2 * j] = a2[j];
        }
    } else {
        dev_fill(0, b - 128, ei, w);
    }
}

// ================= tensor-core sgemm: y_t = xh_t @ Wh_t (fp16 in, fp32 acc) ===
#define BM 64
#define BN 128
#define SGB ((NN + BM - 1) / BM)   // 313
#define ASTRIDE 40
#define BSTRIDE 136

__device__ __forceinline__ void dev_sgemm(int t, int bx, char* sm) {
    __half* Ah = (__half*)sm;                       // [64][ASTRIDE]
    __half* Bh = (__half*)(sm + 64 * ASTRIDE * 2);  // [32][BSTRIDE]
    const __half* A = g_xh + (size_t)t * NN * DIN;
    const __half* B = g_Wh + t * MAT;
    __half* C = g_y + (size_t)t * NN * DOUT;
    int tid = threadIdx.x, lane = tid & 31, wid = tid >> 5;
    int wm = wid >> 2, wq = wid & 3;
    int bm = bx * BM;

    float c[2][4][4];
#pragma unroll
    for (int ma = 0; ma < 2; ma++)
#pragma unroll
        for (int na = 0; na < 4; na++)
#pragma unroll
            for (int i = 0; i < 4; i++) c[ma][na][i] = 0.0f;

    int arow = tid >> 2, acol = (tid & 3) * 8;
    int agr = bm + arow;
    uint4 zero4 = make_uint4(0, 0, 0, 0);

    for (int k0 = 0; k0 < DIN; k0 += 32) {
        uint4 av = (agr < NN) ? *(const uint4*)&A[(size_t)agr * DIN + k0 + acol] : zero4;
        *(uint4*)&Ah[arow * ASTRIDE + acol] = av;
#pragma unroll
        for (int pp = 0; pp < 2; pp++) {
            int q = tid + pp * 256;
            int brr = q >> 4, bcc = (q & 15) * 8;
            *(uint4*)&Bh[brr * BSTRIDE + bcc] = *(const uint4*)&B[(k0 + brr) * BN + bcc];
        }
        __syncthreads();
#pragma unroll
        for (int ks = 0; ks < 32; ks += 16) {
            unsigned bf[4][2];
#pragma unroll
            for (int na = 0; na < 4; na++) {
                int r = ks + (lane & 15);
                unsigned ad = smaddr(&Bh[r * BSTRIDE + wq * 32 + na * 8]);
                asm volatile("ldmatrix.sync.aligned.m8n8.x2.trans.shared.b16 {%0,%1}, [%2];"
                             : "=r"(bf[na][0]), "=r"(bf[na][1]) : "r"(ad));
            }
#pragma unroll
            for (int ma = 0; ma < 2; ma++) {
                int mr = wm * 32 + ma * 16 + (lane & 15);
                int kc = ks + ((lane >> 4) << 3);
                unsigned ad = smaddr(&Ah[mr * ASTRIDE + kc]);
                unsigned a0, a1, a2, a3;
                asm volatile("ldmatrix.sync.aligned.m8n8.x4.shared.b16 {%0,%1,%2,%3}, [%4];"
                             : "=r"(a0), "=r"(a1), "=r"(a2), "=r"(a3) : "r"(ad));
#pragma unroll
                for (int na = 0; na < 4; na++) {
                    asm volatile(
                        "mma.sync.aligned.m16n8k16.row.col.f32.f16.f16.f32 "
                        "{%0,%1,%2,%3}, {%4,%5,%6,%7}, {%8,%9}, {%0,%1,%2,%3};"
                        : "+f"(c[ma][na][0]), "+f"(c[ma][na][1]),
                          "+f"(c[ma][na][2]), "+f"(c[ma][na][3])
                        : "r"(a0), "r"(a1), "r"(a2), "r"(a3),
                          "r"(bf[na][0]), "r"(bf[na][1]));
                }
            }
        }
        __syncthreads();
    }
#pragma unroll
    for (int ma = 0; ma < 2; ma++) {
        int row0 = bm + wm * 32 + ma * 16 + (lane >> 2);
#pragma unroll
        for (int na = 0; na < 4; na++) {
            int col = wq * 32 + na * 8 + (lane & 3) * 2;
            if (row0 < NN)
                *(__half2*)&C[(size_t)row0 * DOUT + col] =
                    __floats2half2_rn(c[ma][na][0], c[ma][na][1]);
            if (row0 + 8 < NN)
                *(__half2*)&C[(size_t)(row0 + 8) * DOUT + col] =
                    __floats2half2_rn(c[ma][na][2], c[ma][na][3]);
        }
    }
}

// ---- gather: 8 edge-rows in flight per warp ----------------------------------
__device__ __forceinline__ void dev_gather(int t, int bx, float* __restrict__ out) {
    int node = bx * 8 + (threadIdx.x >> 5);
    int lane = threadIdx.x & 31;
    const int* off = g_off + t * (NN + 1);
    const int2* csr = g_csr + (size_t)t * EE;
    const __half* y = g_y + (size_t)t * NN * DOUT;
    int beg = off[node], end = off[node + 1];
    float4 acc = make_float4(0.f, 0.f, 0.f, 0.f);
    int e = beg;
    for (; e + 8 <= end; e += 8) {
        int2 cc[8];
        uint2 rr[8];
#pragma unroll
        for (int u = 0; u < 8; u++) cc[u] = csr[e + u];
#pragma unroll
        for (int u = 0; u < 8; u++)
            rr[u] = *(const uint2*)&y[(size_t)cc[u].x * DOUT + lane * 4];
#pragma unroll
        for (int u = 0; u < 8; u++) {
            float wv = __int_as_float(cc[u].y);
            float2 av = __half22float2(*(__half2*)&rr[u].x);
            float2 bv = __half22float2(*(__half2*)&rr[u].y);
            acc.x += wv * av.x;
            acc.y += wv * av.y;
            acc.z += wv * bv.x;
            acc.w += wv * bv.y;
        }
    }
    for (; e < end; e++) {
        int2 c0 = csr[e];
        float w0 = __int_as_float(c0.y);
        uint2 r0 = *(const uint2*)&y[(size_t)c0.x * DOUT + lane * 4];
        float2 a0 = __half22float2(*(__half2*)&r0.x), b0 = __half22float2(*(__half2*)&r0.y);
        acc.x += w0 * a0.x; acc.y += w0 * a0.y; acc.z += w0 * b0.x; acc.w += w0 * b0.y;
    }
    acc.x = (acc.x >= 0.f) ? acc.x : SLOPE * acc.x;
    acc.y = (acc.y >= 0.f) ? acc.y : SLOPE * acc.y;
    acc.z = (acc.z >= 0.f) ? acc.z : SLOPE * acc.z;
    acc.w = (acc.w >= 0.f) ? acc.w : SLOPE * acc.w;
    *(float4*)&out[((size_t)t * NN + node) * DOUT + lane * 4] = acc;
}

// ==== pipe: [gruA(t_sg+1)] | sgemm(t_sg) | [fill(t_fill)] | [gather(t_ga)] ====
#define NGRU 32
#define PIPE_SMEM (KT * 128 * 4 + 2 * KT * 8 * 4)   // 18432 >= sgemm smem 13824
__global__ __launch_bounds__(256, 3)
void pipe_kernel(int t_sg, int t_ga, int t_fill, int ngru,
                 const int* __restrict__ ei, const float* __restrict__ w,
                 const float* __restrict__ bz, const float* __restrict__ br,
                 float* __restrict__ out) {
    __shared__ __align__(16) char sm[PIPE_SMEM];
    int b = blockIdx.x;
    if (b < ngru) { dev_gruA(t_sg + 1, b, bz, br, sm); return; }
    b -= ngru;
    if (b < SGB) { dev_sgemm(t_sg, b, sm); return; }
    b -= SGB;
    if (t_fill >= 0) {
        if (b < 2500) { dev_fill(t_fill, b, ei, w); return; }
        b -= 2500;
    }
    dev_gather(t_ga, b, out);
}

__global__ void gruA0_kernel(const float* __restrict__ bz, const float* __restrict__ br) {
    __shared__ __align__(16) char sm[KT * 128 * 4 + 2 * KT * 8 * 4];
    dev_gruA(0, blockIdx.x, bz, br, sm);
}

__global__ void gather_only_kernel(int t, float* __restrict__ out) {
    dev_gather(t, blockIdx.x, out);
}

// ---------------- launcher ----------------
extern "C" void kernel_launch(void* const* d_in, const int* in_sizes, int n_in,
                              void* d_out, int out_size) {
    const float* node_embs  = (const float*)d_in[0];
    const int*   edge_index = (const int*)d_in[1];
    const float* edge_w     = (const float*)d_in[2];
    const float* mask       = (const float*)d_in[3];
    const float* p          = (const float*)d_in[4];
    const float* Wz         = (const float*)d_in[5];
    const float* Uz         = (const float*)d_in[6];
    const float* bz         = (const float*)d_in[7];
    const float* Wr         = (const float*)d_in[8];
    const float* Ur         = (const float*)d_in[9];
    const float* br         = (const float*)d_in[10];
    const float* Wh         = (const float*)d_in[11];
    const float* Uh         = (const float*)d_in[12];
    const float* bh         = (const float*)d_in[13];
    const float* W0         = (const float*)d_in[14];
    float* out = (float*)d_out;

    front_kernel<<<FB_TOTAL, 256>>>(node_embs, p, mask, edge_index,
                                    Wz, Uz, Wr, Ur, Wh, Uh, W0);
    mid2s_kernel<<<2 * TT, 1024>>>(node_embs);
    wxfill_kernel<<<128 + 2500, 256>>>(edge_index, edge_w);

    gruA0_kernel<<<NGRU, 256>>>(bz, br);
    gruB_kernel<<<NGRU, 256>>>(0, bh);
    // P1: sgemm(0) + gruA(1) + fill(1)
    pipe_kernel<<<NGRU + SGB + 2500, 256>>>(0, -1, 1, NGRU,
                                            edge_index, edge_w, bz, br, out);
    gruB_kernel<<<NGRU, 256>>>(1, bh);
    // P2: sgemm(1) + gruA(2) + fill(2) + gather(0)
    pipe_kernel<<<NGRU + SGB + 2500 + 2500, 256>>>(1, 0, 2, NGRU,
                                                   edge_index, edge_w, bz, br, out);
    gruB_kernel<<<NGRU, 256>>>(2, bh);
    // P3: sgemm(2) + gruA(3) + fill(3) + gather(1)
    pipe_kernel<<<NGRU + SGB + 2500 + 2500, 256>>>(2, 1, 3, NGRU,
                                                   edge_index, edge_w, bz, br, out);
    gruB_kernel<<<NGRU, 256>>>(3, bh);
    // P4: sgemm(3) + gather(2)
    pipe_kernel<<<SGB + 2500, 256>>>(3, 2, -1, 0,
                                     edge_index, edge_w, bz, br, out);
    gather_only_kernel<<<2500, 256>>>(3, out);
}